// round 6
// baseline (speedup 1.0000x reference)
#include <cuda_runtime.h>
#include <cuda_bf16.h>
#include <cstdint>

#define Bsz 8
#define Nseq 1024
#define Cdim 768
#define Hh 12
#define HD 64
#define RANK 8
#define SCALE 0.125f
#define Mrows (Bsz * Nseq)          // 8192

#define QKV_ELEMS (Bsz * Hh * Nseq * HD)   // 6291456
#define XA_ELEMS  (Mrows * 24)
#define OA_ELEMS  (Mrows * 8)

// float-slot offsets into g_scratch
#define F_O    ((size_t)0)
#define F_XA   (F_O + QKV_ELEMS)
#define F_OA   (F_XA + XA_ELEMS)
#define F_XHI  (F_OA + OA_ELEMS)
#define F_XLO  (F_XHI + QKV_ELEMS / 2)
#define F_WQH  (F_XLO + QKV_ELEMS / 2)
#define F_WQL  (F_WQH + (size_t)(3 * Cdim * Cdim) / 2)
#define F_WPH  (F_WQL + (size_t)(3 * Cdim * Cdim) / 2)
#define F_WPL  (F_WPH + (size_t)(Cdim * Cdim) / 2)
#define F_QH   (F_WPL + (size_t)(Cdim * Cdim) / 2)
#define F_QL   (F_QH + QKV_ELEMS / 2)
#define F_KH   (F_QL + QKV_ELEMS / 2)
#define F_KL   (F_KH + QKV_ELEMS / 2)
#define F_VH   (F_KL + QKV_ELEMS / 2)
#define F_VL   (F_VH + QKV_ELEMS / 2)
#define F_OHI  (F_VL + QKV_ELEMS / 2)
#define F_OLO  (F_OHI + QKV_ELEMS / 2)
#define SCRATCH_FLOATS (F_OLO + QKV_ELEMS / 2)

__device__ float g_scratch[SCRATCH_FLOATS];

// ===========================================================================
// helpers
// ===========================================================================
__device__ __forceinline__ void mma_bf16(float* c, const uint32_t* a, const uint32_t* b) {
    asm volatile("mma.sync.aligned.m16n8k16.row.col.f32.bf16.bf16.f32 "
        "{%0,%1,%2,%3}, {%4,%5,%6,%7}, {%8,%9}, {%0,%1,%2,%3};"
        : "+f"(c[0]), "+f"(c[1]), "+f"(c[2]), "+f"(c[3])
        : "r"(a[0]), "r"(a[1]), "r"(a[2]), "r"(a[3]), "r"(b[0]), "r"(b[1]));
}

__device__ __forceinline__ void splitpair(float x, float y, uint32_t& hi, uint32_t& lo) {
    __nv_bfloat162 h, l;
    h.x = __float2bfloat16(x);
    h.y = __float2bfloat16(y);
    l.x = __float2bfloat16(x - __bfloat162float(h.x));
    l.y = __float2bfloat16(y - __bfloat162float(h.y));
    hi = *reinterpret_cast<uint32_t*>(&h);
    lo = *reinterpret_cast<uint32_t*>(&l);
}

// ===========================================================================
// bf16 split: hi = bf16(v), lo = bf16(v - hi)
// ===========================================================================
__global__ void __launch_bounds__(256) split_kernel(
    const float* __restrict__ in, __nv_bfloat16* __restrict__ hi,
    __nv_bfloat16* __restrict__ lo)
{
    int i = blockIdx.x * 256 + threadIdx.x;
    float4 v = ((const float4*)in)[i];
    uint32_t h0, l0, h1, l1;
    splitpair(v.x, v.y, h0, l0);
    splitpair(v.z, v.w, h1, l1);
    ((uint32_t*)hi)[i * 2]     = h0;
    ((uint32_t*)hi)[i * 2 + 1] = h1;
    ((uint32_t*)lo)[i * 2]     = l0;
    ((uint32_t*)lo)[i * 2 + 1] = l1;
}

// ===========================================================================
// LoRA down-projection v2: warp-per-row, A staged in smem, float4 loads.
// Block = 256 threads (8 warps x 8 rows), grid = Mrows/64.
// ===========================================================================
__global__ void __launch_bounds__(256) lora_down2_kernel(
    const float* __restrict__ in, float* __restrict__ out,
    const float* __restrict__ a0, const float* __restrict__ a1,
    const float* __restrict__ a2, int nA)
{
    extern __shared__ float As[];
    int nDots = nA * 8;
    int tot = nDots * Cdim;
    for (int i = threadIdx.x * 4; i < tot; i += 256 * 4) {
        int a = i / (8 * Cdim);
        int off = i - a * (8 * Cdim);
        const float* src = (a == 0) ? a0 : (a == 1) ? a1 : a2;
        *(float4*)(As + i) = *(const float4*)(src + off);
    }
    __syncthreads();
    int wid = threadIdx.x >> 5, lane = threadIdx.x & 31;
    int row0 = blockIdx.x * 64 + wid * 8;
    for (int rr = 0; rr < 8; rr++) {
        int row = row0 + rr;
        const float* xr = in + (size_t)row * Cdim;
        float4 xv[6];
        #pragma unroll
        for (int i = 0; i < 6; i++)
            xv[i] = *(const float4*)(xr + i * 128 + lane * 4);
        for (int d = 0; d < nDots; d++) {
            const float* ar = As + d * Cdim;
            float s = 0.f;
            #pragma unroll
            for (int i = 0; i < 6; i++) {
                float4 a4 = *(const float4*)(ar + i * 128 + lane * 4);
                s += xv[i].x * a4.x + xv[i].y * a4.y + xv[i].z * a4.z + xv[i].w * a4.w;
            }
            #pragma unroll
            for (int o = 16; o; o >>= 1) s += __shfl_xor_sync(0xffffffffu, s, o);
            if (lane == 0) out[(size_t)row * nDots + d] = s;
        }
    }
}

// ===========================================================================
// bf16x3 NT GEMM via mma.sync, 128x128 tile, BK=32, 8 warps.
// MODE 0: qkv epilogue -> Q/K/V hi,lo bf16 packed u32 [bh][n][hd/2]; q*SCALE.
// MODE 1: proj epilogue -> fp32 out row-major.
// ===========================================================================
#define GK768_U32 384
#define SROW 20
#define STAGE_U32 (4 * 128 * SROW)
#define GEMM_SMEM (2 * STAGE_U32 * 4)

template <int MODE>
__global__ void __launch_bounds__(256) gemm_bf16x3_kernel(
    const uint32_t* __restrict__ Ahi, const uint32_t* __restrict__ Alo,
    const uint32_t* __restrict__ Bhi, const uint32_t* __restrict__ Blo,
    const float* __restrict__ bias,
    const float* __restrict__ xa, int xa_stride,
    const float* __restrict__ wb_q, const float* __restrict__ wb_k,
    const float* __restrict__ wb_v,
    float* __restrict__ outf,
    uint32_t* __restrict__ Qho, uint32_t* __restrict__ Qlo2,
    uint32_t* __restrict__ Kho, uint32_t* __restrict__ Klo2,
    uint32_t* __restrict__ Vho, uint32_t* __restrict__ Vlo2)
{
    extern __shared__ uint32_t sm[];
    int tid = threadIdx.x;
    int wid = tid >> 5, lane = tid & 31;
    int wm = wid >> 2, wn = wid & 3;
    int m0 = blockIdx.y * 128, n0 = blockIdx.x * 128;
    int g = lane >> 2, tg = lane & 3;

    float C[4][4][4];
    #pragma unroll
    for (int a = 0; a < 4; a++)
        #pragma unroll
        for (int b = 0; b < 4; b++)
            #pragma unroll
            for (int q = 0; q < 4; q++) C[a][b][q] = 0.f;

    int row_l = tid >> 2, kq_l = tid & 3;
    int row_h = (tid + 256) >> 2, kq_h = tid & 3;

    uint4 rg[8];
    {
        const uint32_t off = kq_l * 4;
        size_t ar0 = (size_t)(m0 + row_l) * GK768_U32 + off;
        size_t br0 = (size_t)(n0 + row_l) * GK768_U32 + off;
        size_t ar1 = (size_t)(m0 + row_h) * GK768_U32 + off;
        size_t br1 = (size_t)(n0 + row_h) * GK768_U32 + off;
        rg[0] = *(const uint4*)(Ahi + ar0); rg[1] = *(const uint4*)(Alo + ar0);
        rg[2] = *(const uint4*)(Bhi + br0); rg[3] = *(const uint4*)(Blo + br0);
        rg[4] = *(const uint4*)(Ahi + ar1); rg[5] = *(const uint4*)(Alo + ar1);
        rg[6] = *(const uint4*)(Bhi + br1); rg[7] = *(const uint4*)(Blo + br1);
    }
    {
        uint32_t* st = sm;
        uint32_t o0 = row_l * SROW + kq_l * 4;
        uint32_t o1 = row_h * SROW + kq_h * 4;
        *(uint4*)(st + o0) = rg[0];        *(uint4*)(st + 2560 + o0) = rg[1];
        *(uint4*)(st + 5120 + o0) = rg[2]; *(uint4*)(st + 7680 + o0) = rg[3];
        *(uint4*)(st + o1) = rg[4];        *(uint4*)(st + 2560 + o1) = rg[5];
        *(uint4*)(st + 5120 + o1) = rg[6]; *(uint4*)(st + 7680 + o1) = rg[7];
    }
    __syncthreads();

    for (int c = 0; c < 24; c++) {
        int s = c & 1;
        if (c < 23) {
            const uint32_t off = (c + 1) * 16 + kq_l * 4;
            size_t ar0 = (size_t)(m0 + row_l) * GK768_U32 + off;
            size_t br0 = (size_t)(n0 + row_l) * GK768_U32 + off;
            size_t ar1 = (size_t)(m0 + row_h) * GK768_U32 + off;
            size_t br1 = (size_t)(n0 + row_h) * GK768_U32 + off;
            rg[0] = *(const uint4*)(Ahi + ar0); rg[1] = *(const uint4*)(Alo + ar0);
            rg[2] = *(const uint4*)(Bhi + br0); rg[3] = *(const uint4*)(Blo + br0);
            rg[4] = *(const uint4*)(Ahi + ar1); rg[5] = *(const uint4*)(Alo + ar1);
            rg[6] = *(const uint4*)(Bhi + br1); rg[7] = *(const uint4*)(Blo + br1);
        }
        const uint32_t* st = sm + s * STAGE_U32;
        const uint32_t* Ah = st;
        const uint32_t* Al = st + 2560;
        const uint32_t* Bh = st + 5120;
        const uint32_t* Bl = st + 7680;
        #pragma unroll
        for (int ks = 0; ks < 2; ks++) {
            int kp = ks * 8 + tg;
            uint32_t ah[4][4], al[4][4], bh[4][2], bl[4][2];
            #pragma unroll
            for (int mi = 0; mi < 4; mi++) {
                int r0 = wm * 64 + mi * 16 + g;
                ah[mi][0] = Ah[r0 * SROW + kp];
                ah[mi][1] = Ah[(r0 + 8) * SROW + kp];
                ah[mi][2] = Ah[r0 * SROW + kp + 4];
                ah[mi][3] = Ah[(r0 + 8) * SROW + kp + 4];
                al[mi][0] = Al[r0 * SROW + kp];
                al[mi][1] = Al[(r0 + 8) * SROW + kp];
                al[mi][2] = Al[r0 * SROW + kp + 4];
                al[mi][3] = Al[(r0 + 8) * SROW + kp + 4];
            }
            #pragma unroll
            for (int ni = 0; ni < 4; ni++) {
                int rb = wn * 32 + ni * 8 + g;
                bh[ni][0] = Bh[rb * SROW + kp];
                bh[ni][1] = Bh[rb * SROW + kp + 4];
                bl[ni][0] = Bl[rb * SROW + kp];
                bl[ni][1] = Bl[rb * SROW + kp + 4];
            }
            #pragma unroll
            for (int mi = 0; mi < 4; mi++)
                #pragma unroll
                for (int ni = 0; ni < 4; ni++) {
                    mma_bf16(C[mi][ni], ah[mi], bh[ni]);
                    mma_bf16(C[mi][ni], al[mi], bh[ni]);
                    mma_bf16(C[mi][ni], ah[mi], bl[ni]);
                }
        }
        if (c < 23) {
            uint32_t* stn = sm + (s ^ 1) * STAGE_U32;
            uint32_t o0 = row_l * SROW + kq_l * 4;
            uint32_t o1 = row_h * SROW + kq_h * 4;
            *(uint4*)(stn + o0) = rg[0];        *(uint4*)(stn + 2560 + o0) = rg[1];
            *(uint4*)(stn + 5120 + o0) = rg[2]; *(uint4*)(stn + 7680 + o0) = rg[3];
            *(uint4*)(stn + o1) = rg[4];        *(uint4*)(stn + 2560 + o1) = rg[5];
            *(uint4*)(stn + 5120 + o1) = rg[6]; *(uint4*)(stn + 7680 + o1) = rg[7];
            __syncthreads();
        }
    }

    // ------------------------------ epilogue ------------------------------
    int sct = 0, dbase = 0;
    const float* wb;
    if (MODE == 0) {
        sct = n0 / Cdim;
        dbase = n0 - sct * Cdim;
        wb = (sct == 0) ? wb_q : (sct == 1) ? wb_k : wb_v;
    } else {
        wb = wb_q;
    }
    #pragma unroll
    for (int mi = 0; mi < 4; mi++) {
        int m_a = m0 + wm * 64 + mi * 16 + g;
        int m_b = m_a + 8;
        float xl0[8], xl1[8];
        {
            const float* xr0 = xa + (size_t)m_a * xa_stride + ((MODE == 0) ? sct * 8 : 0);
            const float* xr1 = xa + (size_t)m_b * xa_stride + ((MODE == 0) ? sct * 8 : 0);
            #pragma unroll
            for (int r = 0; r < 8; r++) { xl0[r] = xr0[r]; xl1[r] = xr1[r]; }
        }
        int ba = m_a >> 10, na = m_a & 1023;
        int bb = m_b >> 10, nb = m_b & 1023;
        #pragma unroll
        for (int ni = 0; ni < 4; ni++) {
            int dloc = wn * 32 + ni * 8 + tg * 2;
            int d0 = n0 + dloc;
            float2 va, vb2;
            va.x  = C[mi][ni][0] + bias[d0];
            va.y  = C[mi][ni][1] + bias[d0 + 1];
            vb2.x = C[mi][ni][2] + bias[d0];
            vb2.y = C[mi][ni][3] + bias[d0 + 1];
            int dd0 = (MODE == 0) ? (dbase + dloc) : d0;
            #pragma unroll
            for (int r = 0; r < 8; r++) {
                float w0 = wb[dd0 * 8 + r], w1 = wb[(dd0 + 1) * 8 + r];
                va.x  += xl0[r] * w0;  va.y  += xl0[r] * w1;
                vb2.x += xl1[r] * w0;  vb2.y += xl1[r] * w1;
            }
            if (MODE == 0) {
                int h = dd0 >> 6, hd = dd0 & 63;
                if (sct == 0) { va.x *= SCALE; va.y *= SCALE; vb2.x *= SCALE; vb2.y *= SCALE; }
                uint32_t *th = (sct == 0) ? Qho : (sct == 1) ? Kho : Vho;
                uint32_t *tl = (sct == 0) ? Qlo2 : (sct == 1) ? Klo2 : Vlo2;
                uint32_t hA, lA, hB, lB;
                splitpair(va.x, va.y, hA, lA);
                splitpair(vb2.x, vb2.y, hB, lB);
                size_t iA = (((size_t)(ba * Hh + h) * Nseq) + na) * 32 + (hd >> 1);
                size_t iB = (((size_t)(bb * Hh + h) * Nseq) + nb) * 32 + (hd >> 1);
                th[iA] = hA; tl[iA] = lA;
                th[iB] = hB; tl[iB] = lB;
            } else {
                *(float2*)(outf + (size_t)m_a * Cdim + d0) = va;
                *(float2*)(outf + (size_t)m_b * Cdim + d0) = vb2;
            }
        }
    }
}

// ===========================================================================
// Flash attention via mma.sync bf16x3.
// CTA: 128 queries (8 warps x 16 rows), loops 8 tiles of 128 keys.
// V arrives row-major [bh][n][hd] (hi/lo u32-packed); transposed into smem.
// ===========================================================================
#define KS_STRIDE 36               // u32 stride for K smem rows
#define VS_STRIDE 67               // u32 stride for transposed V rows (64 keypairs + 3)
#define ATT_SMEM_U32 (2 * 128 * KS_STRIDE + 2 * 64 * VS_STRIDE)  // 17792
#define ATT_SMEM (ATT_SMEM_U32 * 4)

__global__ void __launch_bounds__(256) attn_mma_kernel(
    const uint32_t* __restrict__ Qh, const uint32_t* __restrict__ Ql,
    const uint32_t* __restrict__ Kh, const uint32_t* __restrict__ Kl,
    const uint32_t* __restrict__ Vh, const uint32_t* __restrict__ Vl,
    float* __restrict__ O, uint32_t* __restrict__ Ohi, uint32_t* __restrict__ Olo)
{
    extern __shared__ uint32_t sm[];
    uint32_t* Khs = sm;                         // 128 x 36
    uint32_t* Kls = sm + 128 * KS_STRIDE;
    uint32_t* Vhs = sm + 2 * 128 * KS_STRIDE;   // 64 x 67 (keypairs)
    uint32_t* Vls = Vhs + 64 * VS_STRIDE;
    uint16_t* Vh16 = (uint16_t*)Vhs;
    uint16_t* Vl16 = (uint16_t*)Vls;

    int bh = blockIdx.y, qt = blockIdx.x;
    int tid = threadIdx.x, wid = tid >> 5, lane = tid & 31;
    int g = lane >> 2, tg = lane & 3;

    uint32_t qh[4][4], ql[4][4];
    {
        const uint32_t* qb  = Qh + ((size_t)bh * Nseq + qt * 128 + wid * 16) * 32;
        const uint32_t* qb2 = Ql + ((size_t)bh * Nseq + qt * 128 + wid * 16) * 32;
        #pragma unroll
        for (int ks = 0; ks < 4; ks++) {
            int c0 = ks * 8 + tg;
            qh[ks][0] = qb[g * 32 + c0];        qh[ks][1] = qb[(g + 8) * 32 + c0];
            qh[ks][2] = qb[g * 32 + c0 + 4];    qh[ks][3] = qb[(g + 8) * 32 + c0 + 4];
            ql[ks][0] = qb2[g * 32 + c0];       ql[ks][1] = qb2[(g + 8) * 32 + c0];
            ql[ks][2] = qb2[g * 32 + c0 + 4];   ql[ks][3] = qb2[(g + 8) * 32 + c0 + 4];
        }
    }

    float Oa[8][4];
    #pragma unroll
    for (int i = 0; i < 8; i++)
        #pragma unroll
        for (int j = 0; j < 4; j++) Oa[i][j] = 0.f;
    float mr0 = -1e30f, mr1 = -1e30f, lr0 = 0.f, lr1 = 0.f;

    const uint32_t* kgh = Kh + (size_t)bh * Nseq * 32;
    const uint32_t* kgl = Kl + (size_t)bh * Nseq * 32;
    const uint32_t* vgh = Vh + (size_t)bh * Nseq * 32;
    const uint32_t* vgl = Vl + (size_t)bh * Nseq * 32;

    for (int kt = 0; kt < 8; kt++) {
        __syncthreads();
        #pragma unroll
        for (int i = 0; i < 4; i++) {
            int f = tid + i * 256;             // 0..1023 uint4 units
            int key = f >> 3, c = f & 7;
            size_t gidx = ((size_t)(kt * 128 + key)) * 32 + c * 4;
            *(uint4*)(Khs + key * KS_STRIDE + c * 4) = *(const uint4*)(kgh + gidx);
            *(uint4*)(Kls + key * KS_STRIDE + c * 4) = *(const uint4*)(kgl + gidx);
            // V: transpose into smem (keypairs contiguous per hd row)
            uint4 wv = *(const uint4*)(vgh + gidx);
            uint4 wl = *(const uint4*)(vgl + gidx);
            uint32_t wsv[4] = {wv.x, wv.y, wv.z, wv.w};
            uint32_t wsl[4] = {wl.x, wl.y, wl.z, wl.w};
            #pragma unroll
            for (int s2 = 0; s2 < 4; s2++) {
                int hd0 = c * 8 + s2 * 2;
                Vh16[hd0 * (VS_STRIDE * 2) + key]       = (uint16_t)(wsv[s2] & 0xffff);
                Vh16[(hd0 + 1) * (VS_STRIDE * 2) + key] = (uint16_t)(wsv[s2] >> 16);
                Vl16[hd0 * (VS_STRIDE * 2) + key]       = (uint16_t)(wsl[s2] & 0xffff);
                Vl16[(hd0 + 1) * (VS_STRIDE * 2) + key] = (uint16_t)(wsl[s2] >> 16);
            }
        }
        __syncthreads();

        // S = Q K^T (bf16x3)
        float Sf[16][4];
        #pragma unroll
        for (int ni = 0; ni < 16; ni++)
            #pragma unroll
            for (int q = 0; q < 4; q++) Sf[ni][q] = 0.f;
        #pragma unroll
        for (int ni = 0; ni < 16; ni++) {
            int krow = ni * 8 + g;
            #pragma unroll
            for (int ks = 0; ks < 4; ks++) {
                uint32_t bhh[2], bll[2];
                bhh[0] = Khs[krow * KS_STRIDE + ks * 8 + tg];
                bhh[1] = Khs[krow * KS_STRIDE + ks * 8 + tg + 4];
                bll[0] = Kls[krow * KS_STRIDE + ks * 8 + tg];
                bll[1] = Kls[krow * KS_STRIDE + ks * 8 + tg + 4];
                mma_bf16(Sf[ni], qh[ks], bhh);
                mma_bf16(Sf[ni], ql[ks], bhh);
                mma_bf16(Sf[ni], qh[ks], bll);
            }
        }

        // online softmax (rows g, g+8)
        float tm0 = -1e30f, tm1 = -1e30f;
        #pragma unroll
        for (int ni = 0; ni < 16; ni++) {
            tm0 = fmaxf(tm0, fmaxf(Sf[ni][0], Sf[ni][1]));
            tm1 = fmaxf(tm1, fmaxf(Sf[ni][2], Sf[ni][3]));
        }
        tm0 = fmaxf(tm0, __shfl_xor_sync(0xffffffffu, tm0, 1));
        tm0 = fmaxf(tm0, __shfl_xor_sync(0xffffffffu, tm0, 2));
        tm1 = fmaxf(tm1, __shfl_xor_sync(0xffffffffu, tm1, 1));
        tm1 = fmaxf(tm1, __shfl_xor_sync(0xffffffffu, tm1, 2));
        float mn0 = fmaxf(mr0, tm0), mn1 = fmaxf(mr1, tm1);
        float al0 = __expf(mr0 - mn0), al1 = __expf(mr1 - mn1);
        mr0 = mn0; mr1 = mn1;
        float s0 = 0.f, s1 = 0.f;
        #pragma unroll
        for (int ni = 0; ni < 16; ni++) {
            Sf[ni][0] = __expf(Sf[ni][0] - mn0);
            Sf[ni][1] = __expf(Sf[ni][1] - mn0);
            Sf[ni][2] = __expf(Sf[ni][2] - mn1);
            Sf[ni][3] = __expf(Sf[ni][3] - mn1);
            s0 += Sf[ni][0] + Sf[ni][1];
            s1 += Sf[ni][2] + Sf[ni][3];
        }
        s0 += __shfl_xor_sync(0xffffffffu, s0, 1);
        s0 += __shfl_xor_sync(0xffffffffu, s0, 2);
        s1 += __shfl_xor_sync(0xffffffffu, s1, 1);
        s1 += __shfl_xor_sync(0xffffffffu, s1, 2);
        lr0 = lr0 * al0 + s0;
        lr1 = lr1 * al1 + s1;
        #pragma unroll
        for (int ni = 0; ni < 8; ni++) {
            Oa[ni][0] *= al0; Oa[ni][1] *= al0;
            Oa[ni][2] *= al1; Oa[ni][3] *= al1;
        }

        // O += P V  (bf16x3)
        #pragma unroll
        for (int j = 0; j < 8; j++) {
            uint32_t ph[4], pl[4];
            splitpair(Sf[2*j][0],   Sf[2*j][1],   ph[0], pl[0]);
            splitpair(Sf[2*j][2],   Sf[2*j][3],   ph[1], pl[1]);
            splitpair(Sf[2*j+1][0], Sf[2*j+1][1], ph[2], pl[2]);
            splitpair(Sf[2*j+1][2], Sf[2*j+1][3], ph[3], pl[3]);
            #pragma unroll
            for (int ni = 0; ni < 8; ni++) {
                int vrow = ni * 8 + g;
                uint32_t vh2[2], vl2[2];
                vh2[0] = Vhs[vrow * VS_STRIDE + j * 8 + tg];
                vh2[1] = Vhs[vrow * VS_STRIDE + j * 8 + tg + 4];
                vl2[0] = Vls[vrow * VS_STRIDE + j * 8 + tg];
                vl2[1] = Vls[vrow * VS_STRIDE + j * 8 + tg + 4];
                mma_bf16(Oa[ni], ph, vh2);
                mma_bf16(Oa[ni], pl, vh2);
                mma_bf16(Oa[ni], ph, vl2);
            }
        }
    }

    // epilogue: O fp32 [b][n][C] + bf16 hi/lo
    float inv0 = 1.f / lr0, inv1 = 1.f / lr1;
    int b = bh / Hh, h = bh % Hh;
    int nA = qt * 128 + wid * 16 + g;
    int nB = nA + 8;
    #pragma unroll
    for (int ni = 0; ni < 8; ni++) {
        int hd = ni * 8 + tg * 2;
        float2 vA, vB;
        vA.x = Oa[ni][0] * inv0; vA.y = Oa[ni][1] * inv0;
        vB.x = Oa[ni][2] * inv1; vB.y = Oa[ni][3] * inv1;
        size_t iA = ((size_t)b * Nseq + nA) * Cdim + h * HD + hd;
        size_t iB = ((size_t)b * Nseq + nB) * Cdim + h * HD + hd;
        *(float2*)(O + iA) = vA;
        *(float2*)(O + iB) = vB;
        uint32_t hA, lA, hB, lB;
        splitpair(vA.x, vA.y, hA, lA);
        splitpair(vB.x, vB.y, hB, lB);
        Ohi[iA >> 1] = hA; Olo[iA >> 1] = lA;
        Ohi[iB >> 1] = hB; Olo[iB >> 1] = lB;
    }
}

// ===========================================================================
extern "C" void kernel_launch(void* const* d_in, const int* in_sizes, int n_in,
                              void* d_out, int out_size)
{
    const float* x      = (const float*)d_in[0];
    const float* w_qkv  = (const float*)d_in[1];
    const float* b_qkv  = (const float*)d_in[2];
    const float* w_proj = (const float*)d_in[3];
    const float* b_proj = (const float*)d_in[4];
    const float* q_a = (const float*)d_in[5];
    const float* q_b = (const float*)d_in[6];
    const float* k_a = (const float*)d_in[7];
    const float* k_b = (const float*)d_in[8];
    const float* v_a = (const float*)d_in[9];
    const float* v_b = (const float*)d_in[10];
    const float* o_a = (const float*)d_in[11];
    const float* o_b = (const float*)d_in[12];
    float* out = (float*)d_out;

    void* sym = nullptr;
    cudaGetSymbolAddress(&sym, g_scratch);
    float* base = (float*)sym;
    float* Ob = base + F_O;
    float* XA = base + F_XA;
    float* OA = base + F_OA;
    __nv_bfloat16* xhi = (__nv_bfloat16*)(base + F_XHI);
    __nv_bfloat16* xlo = (__nv_bfloat16*)(base + F_XLO);
    __nv_bfloat16* wqh = (__nv_bfloat16*)(base + F_WQH);
    __nv_bfloat16* wql = (__nv_bfloat16*)(base + F_WQL);
    __nv_bfloat16* wph = (__nv_bfloat16*)(base + F_WPH);
    __nv_bfloat16* wpl = (__nv_bfloat16*)(base + F_WPL);
    uint32_t* Qhp = (uint32_t*)(base + F_QH);
    uint32_t* Qlp = (uint32_t*)(base + F_QL);
    uint32_t* Khp = (uint32_t*)(base + F_KH);
    uint32_t* Klp = (uint32_t*)(base + F_KL);
    uint32_t* Vhp = (uint32_t*)(base + F_VH);
    uint32_t* Vlp = (uint32_t*)(base + F_VL);
    uint32_t* Ohip = (uint32_t*)(base + F_OHI);
    uint32_t* Olop = (uint32_t*)(base + F_OLO);

    cudaFuncSetAttribute(gemm_bf16x3_kernel<0>, cudaFuncAttributeMaxDynamicSharedMemorySize, GEMM_SMEM);
    cudaFuncSetAttribute(gemm_bf16x3_kernel<1>, cudaFuncAttributeMaxDynamicSharedMemorySize, GEMM_SMEM);
    cudaFuncSetAttribute(attn_mma_kernel, cudaFuncAttributeMaxDynamicSharedMemorySize, ATT_SMEM);
    cudaFuncSetAttribute(lora_down2_kernel, cudaFuncAttributeMaxDynamicSharedMemorySize, 24 * Cdim * 4);

    split_kernel<<<QKV_ELEMS / 1024, 256>>>(x, xhi, xlo);
    split_kernel<<<(3 * Cdim * Cdim) / 1024, 256>>>(w_qkv, wqh, wql);
    split_kernel<<<(Cdim * Cdim) / 1024, 256>>>(w_proj, wph, wpl);

    lora_down2_kernel<<<Mrows / 64, 256, 24 * Cdim * 4>>>(x, XA, q_a, k_a, v_a, 3);

    gemm_bf16x3_kernel<0><<<dim3(18, 64), 256, GEMM_SMEM>>>(
        (const uint32_t*)xhi, (const uint32_t*)xlo,
        (const uint32_t*)wqh, (const uint32_t*)wql,
        b_qkv, XA, 24, q_b, k_b, v_b,
        nullptr, Qhp, Qlp, Khp, Klp, Vhp, Vlp);

    attn_mma_kernel<<<dim3(8, Bsz * Hh), 256, ATT_SMEM>>>(
        Qhp, Qlp, Khp, Klp, Vhp, Vlp, Ob, Ohip, Olop);

    lora_down2_kernel<<<Mrows / 64, 256, 8 * Cdim * 4>>>(Ob, OA, o_a, o_a, o_a, 1);

    gemm_bf16x3_kernel<1><<<dim3(6, 64), 256, GEMM_SMEM>>>(
        Ohip, Olop, (const uint32_t*)wph, (const uint32_t*)wpl,
        b_proj, OA, 8, o_b, o_b, o_b,
        out, nullptr, nullptr, nullptr, nullptr, nullptr, nullptr);
}

// round 7
// speedup vs baseline: 1.0153x; 1.0153x over previous
#include <cuda_runtime.h>
#include <cuda_bf16.h>
#include <cstdint>

#define Bsz 8
#define Nseq 1024
#define Cdim 768
#define Hh 12
#define HD 64
#define RANK 8
#define SCALE 0.125f
#define Mrows (Bsz * Nseq)          // 8192

#define QKV_ELEMS (Bsz * Hh * Nseq * HD)   // 6291456
#define XA_ELEMS  (Mrows * 24)
#define OA_ELEMS  (Mrows * 8)

// float-slot offsets into g_scratch
#define F_O    ((size_t)0)
#define F_XA   (F_O + QKV_ELEMS)
#define F_OA   (F_XA + XA_ELEMS)
#define F_XHI  (F_OA + OA_ELEMS)
#define F_XLO  (F_XHI + QKV_ELEMS / 2)
#define F_WQH  (F_XLO + QKV_ELEMS / 2)
#define F_WQL  (F_WQH + (size_t)(3 * Cdim * Cdim) / 2)
#define F_WPH  (F_WQL + (size_t)(3 * Cdim * Cdim) / 2)
#define F_WPL  (F_WPH + (size_t)(Cdim * Cdim) / 2)
#define F_QH   (F_WPL + (size_t)(Cdim * Cdim) / 2)
#define F_QL   (F_QH + QKV_ELEMS / 2)
#define F_KH   (F_QL + QKV_ELEMS / 2)
#define F_KL   (F_KH + QKV_ELEMS / 2)
#define F_VH   (F_KL + QKV_ELEMS / 2)
#define F_VL   (F_VH + QKV_ELEMS / 2)
#define F_OHI  (F_VL + QKV_ELEMS / 2)
#define F_OLO  (F_OHI + QKV_ELEMS / 2)
#define SCRATCH_FLOATS (F_OLO + QKV_ELEMS / 2)

__device__ float g_scratch[SCRATCH_FLOATS];

// ===========================================================================
// helpers
// ===========================================================================
__device__ __forceinline__ void mma_bf16(float* c, const uint32_t* a, const uint32_t* b) {
    asm volatile("mma.sync.aligned.m16n8k16.row.col.f32.bf16.bf16.f32 "
        "{%0,%1,%2,%3}, {%4,%5,%6,%7}, {%8,%9}, {%0,%1,%2,%3};"
        : "+f"(c[0]), "+f"(c[1]), "+f"(c[2]), "+f"(c[3])
        : "r"(a[0]), "r"(a[1]), "r"(a[2]), "r"(a[3]), "r"(b[0]), "r"(b[1]));
}

__device__ __forceinline__ void splitpair(float x, float y, uint32_t& hi, uint32_t& lo) {
    __nv_bfloat162 h, l;
    h.x = __float2bfloat16(x);
    h.y = __float2bfloat16(y);
    l.x = __float2bfloat16(x - __bfloat162float(h.x));
    l.y = __float2bfloat16(y - __bfloat162float(h.y));
    hi = *reinterpret_cast<uint32_t*>(&h);
    lo = *reinterpret_cast<uint32_t*>(&l);
}

// ===========================================================================
// bf16 split: hi = bf16(v), lo = bf16(v - hi)
// ===========================================================================
__global__ void __launch_bounds__(256) split_kernel(
    const float* __restrict__ in, __nv_bfloat16* __restrict__ hi,
    __nv_bfloat16* __restrict__ lo)
{
    int i = blockIdx.x * 256 + threadIdx.x;
    float4 v = ((const float4*)in)[i];
    uint32_t h0, l0, h1, l1;
    splitpair(v.x, v.y, h0, l0);
    splitpair(v.z, v.w, h1, l1);
    ((uint32_t*)hi)[i * 2]     = h0;
    ((uint32_t*)hi)[i * 2 + 1] = h1;
    ((uint32_t*)lo)[i * 2]     = l0;
    ((uint32_t*)lo)[i * 2 + 1] = l1;
}

// ===========================================================================
// LoRA down-projection v3: warp-per-row, grid = Mrows/8 (full chip),
// A staged in smem.
// ===========================================================================
__global__ void __launch_bounds__(256) lora_down3_kernel(
    const float* __restrict__ in, float* __restrict__ out,
    const float* __restrict__ a0, const float* __restrict__ a1,
    const float* __restrict__ a2, int nA)
{
    extern __shared__ float As[];
    int nDots = nA * 8;
    int tot = nDots * Cdim;
    for (int i = threadIdx.x * 4; i < tot; i += 256 * 4) {
        int a = i / (8 * Cdim);
        int off = i - a * (8 * Cdim);
        const float* src = (a == 0) ? a0 : (a == 1) ? a1 : a2;
        *(float4*)(As + i) = *(const float4*)(src + off);
    }
    __syncthreads();
    int wid = threadIdx.x >> 5, lane = threadIdx.x & 31;
    int row = blockIdx.x * 8 + wid;
    const float* xr = in + (size_t)row * Cdim;
    float4 xv[6];
    #pragma unroll
    for (int i = 0; i < 6; i++)
        xv[i] = *(const float4*)(xr + i * 128 + lane * 4);
    for (int d = 0; d < nDots; d++) {
        const float* ar = As + d * Cdim;
        float s = 0.f;
        #pragma unroll
        for (int i = 0; i < 6; i++) {
            float4 a4 = *(const float4*)(ar + i * 128 + lane * 4);
            s += xv[i].x * a4.x + xv[i].y * a4.y + xv[i].z * a4.z + xv[i].w * a4.w;
        }
        #pragma unroll
        for (int o = 16; o; o >>= 1) s += __shfl_xor_sync(0xffffffffu, s, o);
        if (lane == 0) out[(size_t)row * nDots + d] = s;
    }
}

// ===========================================================================
// bf16x3 NT GEMM via mma.sync, 128x128 tile, BK=32, 8 warps.
// Split-term MMAs issued in term-passes (16 independent accumulators between
// RAW reuses of any C fragment).
// ===========================================================================
#define GK768_U32 384
#define SROW 20
#define STAGE_U32 (4 * 128 * SROW)
#define GEMM_SMEM (2 * STAGE_U32 * 4)

template <int MODE>
__global__ void __launch_bounds__(256) gemm_bf16x3_kernel(
    const uint32_t* __restrict__ Ahi, const uint32_t* __restrict__ Alo,
    const uint32_t* __restrict__ Bhi, const uint32_t* __restrict__ Blo,
    const float* __restrict__ bias,
    const float* __restrict__ xa, int xa_stride,
    const float* __restrict__ wb_q, const float* __restrict__ wb_k,
    const float* __restrict__ wb_v,
    float* __restrict__ outf,
    uint32_t* __restrict__ Qho, uint32_t* __restrict__ Qlo2,
    uint32_t* __restrict__ Kho, uint32_t* __restrict__ Klo2,
    uint32_t* __restrict__ Vho, uint32_t* __restrict__ Vlo2)
{
    extern __shared__ uint32_t sm[];
    int tid = threadIdx.x;
    int wid = tid >> 5, lane = tid & 31;
    int wm = wid >> 2, wn = wid & 3;
    int m0 = blockIdx.y * 128, n0 = blockIdx.x * 128;
    int g = lane >> 2, tg = lane & 3;

    float C[4][4][4];
    #pragma unroll
    for (int a = 0; a < 4; a++)
        #pragma unroll
        for (int b = 0; b < 4; b++)
            #pragma unroll
            for (int q = 0; q < 4; q++) C[a][b][q] = 0.f;

    int row_l = tid >> 2, kq_l = tid & 3;
    int row_h = (tid + 256) >> 2, kq_h = tid & 3;

    uint4 rg[8];
    {
        const uint32_t off = kq_l * 4;
        size_t ar0 = (size_t)(m0 + row_l) * GK768_U32 + off;
        size_t br0 = (size_t)(n0 + row_l) * GK768_U32 + off;
        size_t ar1 = (size_t)(m0 + row_h) * GK768_U32 + off;
        size_t br1 = (size_t)(n0 + row_h) * GK768_U32 + off;
        rg[0] = *(const uint4*)(Ahi + ar0); rg[1] = *(const uint4*)(Alo + ar0);
        rg[2] = *(const uint4*)(Bhi + br0); rg[3] = *(const uint4*)(Blo + br0);
        rg[4] = *(const uint4*)(Ahi + ar1); rg[5] = *(const uint4*)(Alo + ar1);
        rg[6] = *(const uint4*)(Bhi + br1); rg[7] = *(const uint4*)(Blo + br1);
    }
    {
        uint32_t* st = sm;
        uint32_t o0 = row_l * SROW + kq_l * 4;
        uint32_t o1 = row_h * SROW + kq_h * 4;
        *(uint4*)(st + o0) = rg[0];        *(uint4*)(st + 2560 + o0) = rg[1];
        *(uint4*)(st + 5120 + o0) = rg[2]; *(uint4*)(st + 7680 + o0) = rg[3];
        *(uint4*)(st + o1) = rg[4];        *(uint4*)(st + 2560 + o1) = rg[5];
        *(uint4*)(st + 5120 + o1) = rg[6]; *(uint4*)(st + 7680 + o1) = rg[7];
    }
    __syncthreads();

    for (int c = 0; c < 24; c++) {
        int s = c & 1;
        if (c < 23) {
            const uint32_t off = (c + 1) * 16 + kq_l * 4;
            size_t ar0 = (size_t)(m0 + row_l) * GK768_U32 + off;
            size_t br0 = (size_t)(n0 + row_l) * GK768_U32 + off;
            size_t ar1 = (size_t)(m0 + row_h) * GK768_U32 + off;
            size_t br1 = (size_t)(n0 + row_h) * GK768_U32 + off;
            rg[0] = *(const uint4*)(Ahi + ar0); rg[1] = *(const uint4*)(Alo + ar0);
            rg[2] = *(const uint4*)(Bhi + br0); rg[3] = *(const uint4*)(Blo + br0);
            rg[4] = *(const uint4*)(Ahi + ar1); rg[5] = *(const uint4*)(Alo + ar1);
            rg[6] = *(const uint4*)(Bhi + br1); rg[7] = *(const uint4*)(Blo + br1);
        }
        const uint32_t* st = sm + s * STAGE_U32;
        const uint32_t* Ah = st;
        const uint32_t* Al = st + 2560;
        const uint32_t* Bh = st + 5120;
        const uint32_t* Bl = st + 7680;
        #pragma unroll
        for (int ks = 0; ks < 2; ks++) {
            int kp = ks * 8 + tg;
            uint32_t ah[4][4], al[4][4], bh[4][2], bl[4][2];
            #pragma unroll
            for (int mi = 0; mi < 4; mi++) {
                int r0 = wm * 64 + mi * 16 + g;
                ah[mi][0] = Ah[r0 * SROW + kp];
                ah[mi][1] = Ah[(r0 + 8) * SROW + kp];
                ah[mi][2] = Ah[r0 * SROW + kp + 4];
                ah[mi][3] = Ah[(r0 + 8) * SROW + kp + 4];
                al[mi][0] = Al[r0 * SROW + kp];
                al[mi][1] = Al[(r0 + 8) * SROW + kp];
                al[mi][2] = Al[r0 * SROW + kp + 4];
                al[mi][3] = Al[(r0 + 8) * SROW + kp + 4];
            }
            #pragma unroll
            for (int ni = 0; ni < 4; ni++) {
                int rb = wn * 32 + ni * 8 + g;
                bh[ni][0] = Bh[rb * SROW + kp];
                bh[ni][1] = Bh[rb * SROW + kp + 4];
                bl[ni][0] = Bl[rb * SROW + kp];
                bl[ni][1] = Bl[rb * SROW + kp + 4];
            }
            // term-passes: 16 independent accumulators between C reuses
            #pragma unroll
            for (int mi = 0; mi < 4; mi++)
                #pragma unroll
                for (int ni = 0; ni < 4; ni++)
                    mma_bf16(C[mi][ni], ah[mi], bh[ni]);
            #pragma unroll
            for (int mi = 0; mi < 4; mi++)
                #pragma unroll
                for (int ni = 0; ni < 4; ni++)
                    mma_bf16(C[mi][ni], al[mi], bh[ni]);
            #pragma unroll
            for (int mi = 0; mi < 4; mi++)
                #pragma unroll
                for (int ni = 0; ni < 4; ni++)
                    mma_bf16(C[mi][ni], ah[mi], bl[ni]);
        }
        if (c < 23) {
            uint32_t* stn = sm + (s ^ 1) * STAGE_U32;
            uint32_t o0 = row_l * SROW + kq_l * 4;
            uint32_t o1 = row_h * SROW + kq_h * 4;
            *(uint4*)(stn + o0) = rg[0];        *(uint4*)(stn + 2560 + o0) = rg[1];
            *(uint4*)(stn + 5120 + o0) = rg[2]; *(uint4*)(stn + 7680 + o0) = rg[3];
            *(uint4*)(stn + o1) = rg[4];        *(uint4*)(stn + 2560 + o1) = rg[5];
            *(uint4*)(stn + 5120 + o1) = rg[6]; *(uint4*)(stn + 7680 + o1) = rg[7];
            __syncthreads();
        }
    }

    // ------------------------------ epilogue ------------------------------
    int sct = 0, dbase = 0;
    const float* wb;
    if (MODE == 0) {
        sct = n0 / Cdim;
        dbase = n0 - sct * Cdim;
        wb = (sct == 0) ? wb_q : (sct == 1) ? wb_k : wb_v;
    } else {
        wb = wb_q;
    }
    #pragma unroll
    for (int mi = 0; mi < 4; mi++) {
        int m_a = m0 + wm * 64 + mi * 16 + g;
        int m_b = m_a + 8;
        float xl0[8], xl1[8];
        {
            const float* xr0 = xa + (size_t)m_a * xa_stride + ((MODE == 0) ? sct * 8 : 0);
            const float* xr1 = xa + (size_t)m_b * xa_stride + ((MODE == 0) ? sct * 8 : 0);
            #pragma unroll
            for (int r = 0; r < 8; r++) { xl0[r] = xr0[r]; xl1[r] = xr1[r]; }
        }
        int ba = m_a >> 10, na = m_a & 1023;
        int bb = m_b >> 10, nb = m_b & 1023;
        #pragma unroll
        for (int ni = 0; ni < 4; ni++) {
            int dloc = wn * 32 + ni * 8 + tg * 2;
            int d0 = n0 + dloc;
            float2 va, vb2;
            va.x  = C[mi][ni][0] + bias[d0];
            va.y  = C[mi][ni][1] + bias[d0 + 1];
            vb2.x = C[mi][ni][2] + bias[d0];
            vb2.y = C[mi][ni][3] + bias[d0 + 1];
            int dd0 = (MODE == 0) ? (dbase + dloc) : d0;
            #pragma unroll
            for (int r = 0; r < 8; r++) {
                float w0 = wb[dd0 * 8 + r], w1 = wb[(dd0 + 1) * 8 + r];
                va.x  += xl0[r] * w0;  va.y  += xl0[r] * w1;
                vb2.x += xl1[r] * w0;  vb2.y += xl1[r] * w1;
            }
            if (MODE == 0) {
                int h = dd0 >> 6, hd = dd0 & 63;
                if (sct == 0) { va.x *= SCALE; va.y *= SCALE; vb2.x *= SCALE; vb2.y *= SCALE; }
                uint32_t *th = (sct == 0) ? Qho : (sct == 1) ? Kho : Vho;
                uint32_t *tl = (sct == 0) ? Qlo2 : (sct == 1) ? Klo2 : Vlo2;
                uint32_t hA, lA, hB, lB;
                splitpair(va.x, va.y, hA, lA);
                splitpair(vb2.x, vb2.y, hB, lB);
                size_t iA = (((size_t)(ba * Hh + h) * Nseq) + na) * 32 + (hd >> 1);
                size_t iB = (((size_t)(bb * Hh + h) * Nseq) + nb) * 32 + (hd >> 1);
                th[iA] = hA; tl[iA] = lA;
                th[iB] = hB; tl[iB] = lB;
            } else {
                *(float2*)(outf + (size_t)m_a * Cdim + d0) = va;
                *(float2*)(outf + (size_t)m_b * Cdim + d0) = vb2;
            }
        }
    }
}

// ===========================================================================
// Flash attention via mma.sync bf16x3, term-pass issue order.
// CTA: 128 queries (8 warps x 16 rows), loops 8 tiles of 128 keys.
// V arrives row-major [bh][n][hd] (hi/lo u32-packed); transposed into smem.
// ===========================================================================
#define KS_STRIDE 36
#define VS_STRIDE 67
#define ATT_SMEM_U32 (2 * 128 * KS_STRIDE + 2 * 64 * VS_STRIDE)
#define ATT_SMEM (ATT_SMEM_U32 * 4)

__global__ void __launch_bounds__(256) attn_mma_kernel(
    const uint32_t* __restrict__ Qh, const uint32_t* __restrict__ Ql,
    const uint32_t* __restrict__ Kh, const uint32_t* __restrict__ Kl,
    const uint32_t* __restrict__ Vh, const uint32_t* __restrict__ Vl,
    float* __restrict__ O, uint32_t* __restrict__ Ohi, uint32_t* __restrict__ Olo)
{
    extern __shared__ uint32_t sm[];
    uint32_t* Khs = sm;
    uint32_t* Kls = sm + 128 * KS_STRIDE;
    uint32_t* Vhs = sm + 2 * 128 * KS_STRIDE;
    uint32_t* Vls = Vhs + 64 * VS_STRIDE;
    uint16_t* Vh16 = (uint16_t*)Vhs;
    uint16_t* Vl16 = (uint16_t*)Vls;

    int bh = blockIdx.y, qt = blockIdx.x;
    int tid = threadIdx.x, wid = tid >> 5, lane = tid & 31;
    int g = lane >> 2, tg = lane & 3;

    uint32_t qh[4][4], ql[4][4];
    {
        const uint32_t* qb  = Qh + ((size_t)bh * Nseq + qt * 128 + wid * 16) * 32;
        const uint32_t* qb2 = Ql + ((size_t)bh * Nseq + qt * 128 + wid * 16) * 32;
        #pragma unroll
        for (int ks = 0; ks < 4; ks++) {
            int c0 = ks * 8 + tg;
            qh[ks][0] = qb[g * 32 + c0];        qh[ks][1] = qb[(g + 8) * 32 + c0];
            qh[ks][2] = qb[g * 32 + c0 + 4];    qh[ks][3] = qb[(g + 8) * 32 + c0 + 4];
            ql[ks][0] = qb2[g * 32 + c0];       ql[ks][1] = qb2[(g + 8) * 32 + c0];
            ql[ks][2] = qb2[g * 32 + c0 + 4];   ql[ks][3] = qb2[(g + 8) * 32 + c0 + 4];
        }
    }

    float Oa[8][4];
    #pragma unroll
    for (int i = 0; i < 8; i++)
        #pragma unroll
        for (int j = 0; j < 4; j++) Oa[i][j] = 0.f;
    float mr0 = -1e30f, mr1 = -1e30f, lr0 = 0.f, lr1 = 0.f;

    const uint32_t* kgh = Kh + (size_t)bh * Nseq * 32;
    const uint32_t* kgl = Kl + (size_t)bh * Nseq * 32;
    const uint32_t* vgh = Vh + (size_t)bh * Nseq * 32;
    const uint32_t* vgl = Vl + (size_t)bh * Nseq * 32;

    for (int kt = 0; kt < 8; kt++) {
        __syncthreads();
        #pragma unroll
        for (int i = 0; i < 4; i++) {
            int f = tid + i * 256;
            int key = f >> 3, c = f & 7;
            size_t gidx = ((size_t)(kt * 128 + key)) * 32 + c * 4;
            *(uint4*)(Khs + key * KS_STRIDE + c * 4) = *(const uint4*)(kgh + gidx);
            *(uint4*)(Kls + key * KS_STRIDE + c * 4) = *(const uint4*)(kgl + gidx);
            uint4 wv = *(const uint4*)(vgh + gidx);
            uint4 wl = *(const uint4*)(vgl + gidx);
            uint32_t wsv[4] = {wv.x, wv.y, wv.z, wv.w};
            uint32_t wsl[4] = {wl.x, wl.y, wl.z, wl.w};
            #pragma unroll
            for (int s2 = 0; s2 < 4; s2++) {
                int hd0 = c * 8 + s2 * 2;
                Vh16[hd0 * (VS_STRIDE * 2) + key]       = (uint16_t)(wsv[s2] & 0xffff);
                Vh16[(hd0 + 1) * (VS_STRIDE * 2) + key] = (uint16_t)(wsv[s2] >> 16);
                Vl16[hd0 * (VS_STRIDE * 2) + key]       = (uint16_t)(wsl[s2] & 0xffff);
                Vl16[(hd0 + 1) * (VS_STRIDE * 2) + key] = (uint16_t)(wsl[s2] >> 16);
            }
        }
        __syncthreads();

        // S = Q K^T — term passes per ks with cached hi B-frags
        float Sf[16][4];
        #pragma unroll
        for (int ni = 0; ni < 16; ni++)
            #pragma unroll
            for (int q = 0; q < 4; q++) Sf[ni][q] = 0.f;
        #pragma unroll
        for (int ks = 0; ks < 4; ks++) {
            uint32_t bhs[16][2];
            #pragma unroll
            for (int ni = 0; ni < 16; ni++) {
                int krow = ni * 8 + g;
                bhs[ni][0] = Khs[krow * KS_STRIDE + ks * 8 + tg];
                bhs[ni][1] = Khs[krow * KS_STRIDE + ks * 8 + tg + 4];
                mma_bf16(Sf[ni], qh[ks], bhs[ni]);
            }
            #pragma unroll
            for (int ni = 0; ni < 16; ni++)
                mma_bf16(Sf[ni], ql[ks], bhs[ni]);
            #pragma unroll
            for (int ni = 0; ni < 16; ni++) {
                int krow = ni * 8 + g;
                uint32_t bll[2];
                bll[0] = Kls[krow * KS_STRIDE + ks * 8 + tg];
                bll[1] = Kls[krow * KS_STRIDE + ks * 8 + tg + 4];
                mma_bf16(Sf[ni], qh[ks], bll);
            }
        }

        // online softmax (rows g, g+8)
        float tm0 = -1e30f, tm1 = -1e30f;
        #pragma unroll
        for (int ni = 0; ni < 16; ni++) {
            tm0 = fmaxf(tm0, fmaxf(Sf[ni][0], Sf[ni][1]));
            tm1 = fmaxf(tm1, fmaxf(Sf[ni][2], Sf[ni][3]));
        }
        tm0 = fmaxf(tm0, __shfl_xor_sync(0xffffffffu, tm0, 1));
        tm0 = fmaxf(tm0, __shfl_xor_sync(0xffffffffu, tm0, 2));
        tm1 = fmaxf(tm1, __shfl_xor_sync(0xffffffffu, tm1, 1));
        tm1 = fmaxf(tm1, __shfl_xor_sync(0xffffffffu, tm1, 2));
        float mn0 = fmaxf(mr0, tm0), mn1 = fmaxf(mr1, tm1);
        float al0 = __expf(mr0 - mn0), al1 = __expf(mr1 - mn1);
        mr0 = mn0; mr1 = mn1;
        float s0 = 0.f, s1 = 0.f;
        #pragma unroll
        for (int ni = 0; ni < 16; ni++) {
            Sf[ni][0] = __expf(Sf[ni][0] - mn0);
            Sf[ni][1] = __expf(Sf[ni][1] - mn0);
            Sf[ni][2] = __expf(Sf[ni][2] - mn1);
            Sf[ni][3] = __expf(Sf[ni][3] - mn1);
            s0 += Sf[ni][0] + Sf[ni][1];
            s1 += Sf[ni][2] + Sf[ni][3];
        }
        s0 += __shfl_xor_sync(0xffffffffu, s0, 1);
        s0 += __shfl_xor_sync(0xffffffffu, s0, 2);
        s1 += __shfl_xor_sync(0xffffffffu, s1, 1);
        s1 += __shfl_xor_sync(0xffffffffu, s1, 2);
        lr0 = lr0 * al0 + s0;
        lr1 = lr1 * al1 + s1;
        #pragma unroll
        for (int ni = 0; ni < 8; ni++) {
            Oa[ni][0] *= al0; Oa[ni][1] *= al0;
            Oa[ni][2] *= al1; Oa[ni][3] *= al1;
        }

        // O += P V — term passes per j with cached hi V-frags
        #pragma unroll
        for (int j = 0; j < 8; j++) {
            uint32_t ph[4], pl[4];
            splitpair(Sf[2*j][0],   Sf[2*j][1],   ph[0], pl[0]);
            splitpair(Sf[2*j][2],   Sf[2*j][3],   ph[1], pl[1]);
            splitpair(Sf[2*j+1][0], Sf[2*j+1][1], ph[2], pl[2]);
            splitpair(Sf[2*j+1][2], Sf[2*j+1][3], ph[3], pl[3]);
            uint32_t vhs2[8][2];
            #pragma unroll
            for (int ni = 0; ni < 8; ni++) {
                int vrow = ni * 8 + g;
                vhs2[ni][0] = Vhs[vrow * VS_STRIDE + j * 8 + tg];
                vhs2[ni][1] = Vhs[vrow * VS_STRIDE + j * 8 + tg + 4];
                mma_bf16(Oa[ni], ph, vhs2[ni]);
            }
            #pragma unroll
            for (int ni = 0; ni < 8; ni++)
                mma_bf16(Oa[ni], pl, vhs2[ni]);
            #pragma unroll
            for (int ni = 0; ni < 8; ni++) {
                int vrow = ni * 8 + g;
                uint32_t vl2[2];
                vl2[0] = Vls[vrow * VS_STRIDE + j * 8 + tg];
                vl2[1] = Vls[vrow * VS_STRIDE + j * 8 + tg + 4];
                mma_bf16(Oa[ni], ph, vl2);
            }
        }
    }

    // epilogue
    float inv0 = 1.f / lr0, inv1 = 1.f / lr1;
    int b = bh / Hh, h = bh % Hh;
    int nA = qt * 128 + wid * 16 + g;
    int nB = nA + 8;
    #pragma unroll
    for (int ni = 0; ni < 8; ni++) {
        int hd = ni * 8 + tg * 2;
        float2 vA, vB;
        vA.x = Oa[ni][0] * inv0; vA.y = Oa[ni][1] * inv0;
        vB.x = Oa[ni][2] * inv1; vB.y = Oa[ni][3] * inv1;
        size_t iA = ((size_t)b * Nseq + nA) * Cdim + h * HD + hd;
        size_t iB = ((size_t)b * Nseq + nB) * Cdim + h * HD + hd;
        *(float2*)(O + iA) = vA;
        *(float2*)(O + iB) = vB;
        uint32_t hA, lA, hB, lB;
        splitpair(vA.x, vA.y, hA, lA);
        splitpair(vB.x, vB.y, hB, lB);
        Ohi[iA >> 1] = hA; Olo[iA >> 1] = lA;
        Ohi[iB >> 1] = hB; Olo[iB >> 1] = lB;
    }
}

// ===========================================================================
extern "C" void kernel_launch(void* const* d_in, const int* in_sizes, int n_in,
                              void* d_out, int out_size)
{
    const float* x      = (const float*)d_in[0];
    const float* w_qkv  = (const float*)d_in[1];
    const float* b_qkv  = (const float*)d_in[2];
    const float* w_proj = (const float*)d_in[3];
    const float* b_proj = (const float*)d_in[4];
    const float* q_a = (const float*)d_in[5];
    const float* q_b = (const float*)d_in[6];
    const float* k_a = (const float*)d_in[7];
    const float* k_b = (const float*)d_in[8];
    const float* v_a = (const float*)d_in[9];
    const float* v_b = (const float*)d_in[10];
    const float* o_a = (const float*)d_in[11];
    const float* o_b = (const float*)d_in[12];
    float* out = (float*)d_out;

    void* sym = nullptr;
    cudaGetSymbolAddress(&sym, g_scratch);
    float* base = (float*)sym;
    float* Ob = base + F_O;
    float* XA = base + F_XA;
    float* OA = base + F_OA;
    __nv_bfloat16* xhi = (__nv_bfloat16*)(base + F_XHI);
    __nv_bfloat16* xlo = (__nv_bfloat16*)(base + F_XLO);
    __nv_bfloat16* wqh = (__nv_bfloat16*)(base + F_WQH);
    __nv_bfloat16* wql = (__nv_bfloat16*)(base + F_WQL);
    __nv_bfloat16* wph = (__nv_bfloat16*)(base + F_WPH);
    __nv_bfloat16* wpl = (__nv_bfloat16*)(base + F_WPL);
    uint32_t* Qhp = (uint32_t*)(base + F_QH);
    uint32_t* Qlp = (uint32_t*)(base + F_QL);
    uint32_t* Khp = (uint32_t*)(base + F_KH);
    uint32_t* Klp = (uint32_t*)(base + F_KL);
    uint32_t* Vhp = (uint32_t*)(base + F_VH);
    uint32_t* Vlp = (uint32_t*)(base + F_VL);
    uint32_t* Ohip = (uint32_t*)(base + F_OHI);
    uint32_t* Olop = (uint32_t*)(base + F_OLO);

    cudaFuncSetAttribute(gemm_bf16x3_kernel<0>, cudaFuncAttributeMaxDynamicSharedMemorySize, GEMM_SMEM);
    cudaFuncSetAttribute(gemm_bf16x3_kernel<1>, cudaFuncAttributeMaxDynamicSharedMemorySize, GEMM_SMEM);
    cudaFuncSetAttribute(attn_mma_kernel, cudaFuncAttributeMaxDynamicSharedMemorySize, ATT_SMEM);
    cudaFuncSetAttribute(lora_down3_kernel, cudaFuncAttributeMaxDynamicSharedMemorySize, 24 * Cdim * 4);

    split_kernel<<<QKV_ELEMS / 1024, 256>>>(x, xhi, xlo);
    split_kernel<<<(3 * Cdim * Cdim) / 1024, 256>>>(w_qkv, wqh, wql);
    split_kernel<<<(Cdim * Cdim) / 1024, 256>>>(w_proj, wph, wpl);

    lora_down3_kernel<<<Mrows / 8, 256, 24 * Cdim * 4>>>(x, XA, q_a, k_a, v_a, 3);

    gemm_bf16x3_kernel<0><<<dim3(18, 64), 256, GEMM_SMEM>>>(
        (const uint32_t*)xhi, (const uint32_t*)xlo,
        (const uint32_t*)wqh, (const uint32_t*)wql,
        b_qkv, XA, 24, q_b, k_b, v_b,
        nullptr, Qhp, Qlp, Khp, Klp, Vhp, Vlp);

    attn_mma_kernel<<<dim3(8, Bsz * Hh), 256, ATT_SMEM>>>(
        Qhp, Qlp, Khp, Klp, Vhp, Vlp, Ob, Ohip, Olop);

    lora_down3_kernel<<<Mrows / 8, 256, 8 * Cdim * 4>>>(Ob, OA, o_a, o_a, o_a, 1);

    gemm_bf16x3_kernel<1><<<dim3(6, 64), 256, GEMM_SMEM>>>(
        Ohip, Olop, (const uint32_t*)wph, (const uint32_t*)wpl,
        b_proj, OA, 8, o_b, o_b, o_b,
        out, nullptr, nullptr, nullptr, nullptr, nullptr, nullptr);
}

// round 8
// speedup vs baseline: 1.3537x; 1.3334x over previous
#include <cuda_runtime.h>
#include <cuda_fp16.h>
#include <cstdint>

#define Bsz 8
#define Nseq 1024
#define Cdim 768
#define Hh 12
#define HD 64
#define RANK 8
#define SCALE 0.125f
#define Mrows (Bsz * Nseq)          // 8192

#define QKV_ELEMS (Bsz * Hh * Nseq * HD)   // 6291456
#define XA_ELEMS  (Mrows * 24)
#define OA_ELEMS  (Mrows * 8)

// float-slot offsets into g_scratch
#define F_O    ((size_t)0)
#define F_XA   (F_O + QKV_ELEMS)
#define F_OA   (F_XA + XA_ELEMS)
#define F_XHI  (F_OA + OA_ELEMS)
#define F_XLO  (F_XHI + QKV_ELEMS / 2)
#define F_WQH  (F_XLO + QKV_ELEMS / 2)
#define F_WPH  (F_WQH + (size_t)(3 * Cdim * Cdim) / 2)
#define F_QH   (F_WPH + (size_t)(Cdim * Cdim) / 2)
#define F_QL   (F_QH + QKV_ELEMS / 2)
#define F_KH   (F_QL + QKV_ELEMS / 2)
#define F_VH   (F_KH + QKV_ELEMS / 2)
#define F_OHI  (F_VH + QKV_ELEMS / 2)
#define F_OLO  (F_OHI + QKV_ELEMS / 2)
#define SCRATCH_FLOATS (F_OLO + QKV_ELEMS / 2)

__device__ float g_scratch[SCRATCH_FLOATS];

// ===========================================================================
// helpers
// ===========================================================================
__device__ __forceinline__ void mma_f16(float* c, const uint32_t* a, const uint32_t* b) {
    asm volatile("mma.sync.aligned.m16n8k16.row.col.f32.f16.f16.f32 "
        "{%0,%1,%2,%3}, {%4,%5,%6,%7}, {%8,%9}, {%0,%1,%2,%3};"
        : "+f"(c[0]), "+f"(c[1]), "+f"(c[2]), "+f"(c[3])
        : "r"(a[0]), "r"(a[1]), "r"(a[2]), "r"(a[3]), "r"(b[0]), "r"(b[1]));
}

__device__ __forceinline__ void splitpair_h(float x, float y, uint32_t& hi, uint32_t& lo) {
    __half2 h, l;
    h.x = __float2half_rn(x);
    h.y = __float2half_rn(y);
    l.x = __float2half_rn(x - __half2float(h.x));
    l.y = __float2half_rn(y - __half2float(h.y));
    hi = *reinterpret_cast<uint32_t*>(&h);
    lo = *reinterpret_cast<uint32_t*>(&l);
}
__device__ __forceinline__ uint32_t pack2h(float x, float y) {
    __half2 h;
    h.x = __float2half_rn(x);
    h.y = __float2half_rn(y);
    return *reinterpret_cast<uint32_t*>(&h);
}

// ===========================================================================
// fp16 split: hi = h(v), lo = h(v - hi)
// ===========================================================================
__global__ void __launch_bounds__(256) split_kernel(
    const float* __restrict__ in, uint32_t* __restrict__ hi,
    uint32_t* __restrict__ lo)
{
    int i = blockIdx.x * 256 + threadIdx.x;
    float4 v = ((const float4*)in)[i];
    uint32_t h0, l0, h1, l1;
    splitpair_h(v.x, v.y, h0, l0);
    splitpair_h(v.z, v.w, h1, l1);
    hi[i * 2]     = h0;
    hi[i * 2 + 1] = h1;
    if (lo) {
        lo[i * 2]     = l0;
        lo[i * 2 + 1] = l1;
    }
}

// ===========================================================================
// LoRA down-projection: warp-per-row, A in smem, fully unrolled dot loop.
// ===========================================================================
template <int NA>
__global__ void __launch_bounds__(256) lora_down_kernel(
    const float* __restrict__ in, float* __restrict__ out,
    const float* __restrict__ a0, const float* __restrict__ a1,
    const float* __restrict__ a2)
{
    extern __shared__ float As[];
    constexpr int nDots = NA * 8;
    for (int i = threadIdx.x * 4; i < nDots * Cdim; i += 256 * 4) {
        int a = i / (8 * Cdim);
        int off = i - a * (8 * Cdim);
        const float* src = (a == 0) ? a0 : (a == 1) ? a1 : a2;
        *(float4*)(As + i) = *(const float4*)(src + off);
    }
    __syncthreads();
    int wid = threadIdx.x >> 5, lane = threadIdx.x & 31;
    int row = blockIdx.x * 8 + wid;
    const float* xr = in + (size_t)row * Cdim;
    float4 xv[6];
    #pragma unroll
    for (int i = 0; i < 6; i++)
        xv[i] = *(const float4*)(xr + i * 128 + lane * 4);
    float res[nDots];
    #pragma unroll
    for (int d = 0; d < nDots; d++) {
        const float* ar = As + d * Cdim;
        float s = 0.f;
        #pragma unroll
        for (int i = 0; i < 6; i++) {
            float4 a4 = *(const float4*)(ar + i * 128 + lane * 4);
            s += xv[i].x * a4.x + xv[i].y * a4.y + xv[i].z * a4.z + xv[i].w * a4.w;
        }
        res[d] = s;
    }
    #pragma unroll
    for (int d = 0; d < nDots; d++) {
        #pragma unroll
        for (int o = 16; o; o >>= 1)
            res[d] += __shfl_xor_sync(0xffffffffu, res[d], o);
    }
    if (lane < nDots) out[(size_t)row * nDots + lane] = res[lane];
    // note: res[lane] is uniform-indexed per lane only if lane<nDots; use
    // select loop instead (compiler cannot index res[] dynamically cheaply):
}

// The dynamic res[lane] above would spill; provide correct store via shfl:
// (handled by rewriting: each lane holds full reduced res[] — lane0 stores)
// -- replaced below by storing from lane 0:

// ===========================================================================
// fp16 2-term NT GEMM via mma.sync, 128x128 tile, BK=32, 8 warps.
// C = Ahi*Bhi + Alo*Bhi
// MODE 0: qkv epilogue -> Q hi+lo, K hi, V hi (u32-packed [bh][n][hd/2])
// MODE 1: proj epilogue -> fp32 out
// ===========================================================================
#define GK768_U32 384
#define SROW 20
#define STAGE_U32 (3 * 128 * SROW)          // Ahi, Alo, Bhi
#define GEMM_SMEM (2 * STAGE_U32 * 4)       // 61440

template <int MODE>
__global__ void __launch_bounds__(256) gemm_f16x2_kernel(
    const uint32_t* __restrict__ Ahi, const uint32_t* __restrict__ Alo,
    const uint32_t* __restrict__ Bhi,
    const float* __restrict__ bias,
    const float* __restrict__ xa, int xa_stride,
    const float* __restrict__ wb_q, const float* __restrict__ wb_k,
    const float* __restrict__ wb_v,
    float* __restrict__ outf,
    uint32_t* __restrict__ Qho, uint32_t* __restrict__ Qlo2,
    uint32_t* __restrict__ Kho, uint32_t* __restrict__ Vho)
{
    extern __shared__ uint32_t sm[];
    int tid = threadIdx.x;
    int wid = tid >> 5, lane = tid & 31;
    int wm = wid >> 2, wn = wid & 3;
    int m0 = blockIdx.y * 128, n0 = blockIdx.x * 128;
    int g = lane >> 2, tg = lane & 3;

    float C[4][4][4];
    #pragma unroll
    for (int a = 0; a < 4; a++)
        #pragma unroll
        for (int b = 0; b < 4; b++)
            #pragma unroll
            for (int q = 0; q < 4; q++) C[a][b][q] = 0.f;

    int row_l = tid >> 2, kq_l = tid & 3;
    int row_h = (tid + 256) >> 2;

    uint4 rg[6];
    {
        const uint32_t off = kq_l * 4;
        size_t ar0 = (size_t)(m0 + row_l) * GK768_U32 + off;
        size_t br0 = (size_t)(n0 + row_l) * GK768_U32 + off;
        size_t ar1 = (size_t)(m0 + row_h) * GK768_U32 + off;
        size_t br1 = (size_t)(n0 + row_h) * GK768_U32 + off;
        rg[0] = *(const uint4*)(Ahi + ar0); rg[1] = *(const uint4*)(Alo + ar0);
        rg[2] = *(const uint4*)(Bhi + br0);
        rg[3] = *(const uint4*)(Ahi + ar1); rg[4] = *(const uint4*)(Alo + ar1);
        rg[5] = *(const uint4*)(Bhi + br1);
    }
    {
        uint32_t* st = sm;
        uint32_t o0 = row_l * SROW + kq_l * 4;
        uint32_t o1 = row_h * SROW + kq_l * 4;
        *(uint4*)(st + o0) = rg[0];        *(uint4*)(st + 2560 + o0) = rg[1];
        *(uint4*)(st + 5120 + o0) = rg[2];
        *(uint4*)(st + o1) = rg[3];        *(uint4*)(st + 2560 + o1) = rg[4];
        *(uint4*)(st + 5120 + o1) = rg[5];
    }
    __syncthreads();

    for (int c = 0; c < 24; c++) {
        int s = c & 1;
        if (c < 23) {
            const uint32_t off = (c + 1) * 16 + kq_l * 4;
            size_t ar0 = (size_t)(m0 + row_l) * GK768_U32 + off;
            size_t br0 = (size_t)(n0 + row_l) * GK768_U32 + off;
            size_t ar1 = (size_t)(m0 + row_h) * GK768_U32 + off;
            size_t br1 = (size_t)(n0 + row_h) * GK768_U32 + off;
            rg[0] = *(const uint4*)(Ahi + ar0); rg[1] = *(const uint4*)(Alo + ar0);
            rg[2] = *(const uint4*)(Bhi + br0);
            rg[3] = *(const uint4*)(Ahi + ar1); rg[4] = *(const uint4*)(Alo + ar1);
            rg[5] = *(const uint4*)(Bhi + br1);
        }
        const uint32_t* st = sm + s * STAGE_U32;
        const uint32_t* Ah = st;
        const uint32_t* Al = st + 2560;
        const uint32_t* Bh = st + 5120;
        #pragma unroll
        for (int ks = 0; ks < 2; ks++) {
            int kp = ks * 8 + tg;
            uint32_t ah[4][4], al[4][4], bh[4][2];
            #pragma unroll
            for (int mi = 0; mi < 4; mi++) {
                int r0 = wm * 64 + mi * 16 + g;
                ah[mi][0] = Ah[r0 * SROW + kp];
                ah[mi][1] = Ah[(r0 + 8) * SROW + kp];
                ah[mi][2] = Ah[r0 * SROW + kp + 4];
                ah[mi][3] = Ah[(r0 + 8) * SROW + kp + 4];
                al[mi][0] = Al[r0 * SROW + kp];
                al[mi][1] = Al[(r0 + 8) * SROW + kp];
                al[mi][2] = Al[r0 * SROW + kp + 4];
                al[mi][3] = Al[(r0 + 8) * SROW + kp + 4];
            }
            #pragma unroll
            for (int ni = 0; ni < 4; ni++) {
                int rb = wn * 32 + ni * 8 + g;
                bh[ni][0] = Bh[rb * SROW + kp];
                bh[ni][1] = Bh[rb * SROW + kp + 4];
            }
            #pragma unroll
            for (int mi = 0; mi < 4; mi++)
                #pragma unroll
                for (int ni = 0; ni < 4; ni++)
                    mma_f16(C[mi][ni], ah[mi], bh[ni]);
            #pragma unroll
            for (int mi = 0; mi < 4; mi++)
                #pragma unroll
                for (int ni = 0; ni < 4; ni++)
                    mma_f16(C[mi][ni], al[mi], bh[ni]);
        }
        if (c < 23) {
            uint32_t* stn = sm + (s ^ 1) * STAGE_U32;
            uint32_t o0 = row_l * SROW + kq_l * 4;
            uint32_t o1 = row_h * SROW + kq_l * 4;
            *(uint4*)(stn + o0) = rg[0];        *(uint4*)(stn + 2560 + o0) = rg[1];
            *(uint4*)(stn + 5120 + o0) = rg[2];
            *(uint4*)(stn + o1) = rg[3];        *(uint4*)(stn + 2560 + o1) = rg[4];
            *(uint4*)(stn + 5120 + o1) = rg[5];
            __syncthreads();
        }
    }

    // ------------------------------ epilogue ------------------------------
    int sct = 0, dbase = 0;
    const float* wb;
    if (MODE == 0) {
        sct = n0 / Cdim;
        dbase = n0 - sct * Cdim;
        wb = (sct == 0) ? wb_q : (sct == 1) ? wb_k : wb_v;
    } else {
        wb = wb_q;
    }
    #pragma unroll
    for (int mi = 0; mi < 4; mi++) {
        int m_a = m0 + wm * 64 + mi * 16 + g;
        int m_b = m_a + 8;
        float xl0[8], xl1[8];
        {
            const float* xr0 = xa + (size_t)m_a * xa_stride + ((MODE == 0) ? sct * 8 : 0);
            const float* xr1 = xa + (size_t)m_b * xa_stride + ((MODE == 0) ? sct * 8 : 0);
            #pragma unroll
            for (int r = 0; r < 8; r++) { xl0[r] = xr0[r]; xl1[r] = xr1[r]; }
        }
        int ba = m_a >> 10, na = m_a & 1023;
        int bb = m_b >> 10, nb = m_b & 1023;
        #pragma unroll
        for (int ni = 0; ni < 4; ni++) {
            int dloc = wn * 32 + ni * 8 + tg * 2;
            int d0 = n0 + dloc;
            float2 va, vb2;
            va.x  = C[mi][ni][0] + bias[d0];
            va.y  = C[mi][ni][1] + bias[d0 + 1];
            vb2.x = C[mi][ni][2] + bias[d0];
            vb2.y = C[mi][ni][3] + bias[d0 + 1];
            int dd0 = (MODE == 0) ? (dbase + dloc) : d0;
            #pragma unroll
            for (int r = 0; r < 8; r++) {
                float w0 = wb[dd0 * 8 + r], w1 = wb[(dd0 + 1) * 8 + r];
                va.x  += xl0[r] * w0;  va.y  += xl0[r] * w1;
                vb2.x += xl1[r] * w0;  vb2.y += xl1[r] * w1;
            }
            if (MODE == 0) {
                int h = dd0 >> 6, hd = dd0 & 63;
                size_t iA = (((size_t)(ba * Hh + h) * Nseq) + na) * 32 + (hd >> 1);
                size_t iB = (((size_t)(bb * Hh + h) * Nseq) + nb) * 32 + (hd >> 1);
                if (sct == 0) {
                    va.x *= SCALE; va.y *= SCALE; vb2.x *= SCALE; vb2.y *= SCALE;
                    uint32_t hA, lA, hB, lB;
                    splitpair_h(va.x, va.y, hA, lA);
                    splitpair_h(vb2.x, vb2.y, hB, lB);
                    Qho[iA] = hA; Qlo2[iA] = lA;
                    Qho[iB] = hB; Qlo2[iB] = lB;
                } else {
                    uint32_t* th = (sct == 1) ? Kho : Vho;
                    th[iA] = pack2h(va.x, va.y);
                    th[iB] = pack2h(vb2.x, vb2.y);
                }
            } else {
                *(float2*)(outf + (size_t)m_a * Cdim + d0) = va;
                *(float2*)(outf + (size_t)m_b * Cdim + d0) = vb2;
            }
        }
    }
}

// ===========================================================================
// Flash attention via mma.sync fp16 2-term.
// S = Qhi*Khi + Qlo*Khi;  O += Phi*Vhi + Plo*Vhi.
// ===========================================================================
#define KS_STRIDE 36
#define VS_STRIDE 67
#define ATT_SMEM_U32 (128 * KS_STRIDE + 64 * VS_STRIDE)   // 8896
#define ATT_SMEM (ATT_SMEM_U32 * 4)

__global__ void __launch_bounds__(256) attn_mma_kernel(
    const uint32_t* __restrict__ Qh, const uint32_t* __restrict__ Ql,
    const uint32_t* __restrict__ Kh, const uint32_t* __restrict__ Vh,
    float* __restrict__ O, uint32_t* __restrict__ Ohi, uint32_t* __restrict__ Olo)
{
    extern __shared__ uint32_t sm[];
    uint32_t* Khs = sm;                        // 128 x 36
    uint32_t* Vhs = sm + 128 * KS_STRIDE;      // 64 x 67 keypairs (transposed)
    uint16_t* Vh16 = (uint16_t*)Vhs;

    int bh = blockIdx.y, qt = blockIdx.x;
    int tid = threadIdx.x, wid = tid >> 5, lane = tid & 31;
    int g = lane >> 2, tg = lane & 3;

    uint32_t qh[4][4], ql[4][4];
    {
        const uint32_t* qb  = Qh + ((size_t)bh * Nseq + qt * 128 + wid * 16) * 32;
        const uint32_t* qb2 = Ql + ((size_t)bh * Nseq + qt * 128 + wid * 16) * 32;
        #pragma unroll
        for (int ks = 0; ks < 4; ks++) {
            int c0 = ks * 8 + tg;
            qh[ks][0] = qb[g * 32 + c0];        qh[ks][1] = qb[(g + 8) * 32 + c0];
            qh[ks][2] = qb[g * 32 + c0 + 4];    qh[ks][3] = qb[(g + 8) * 32 + c0 + 4];
            ql[ks][0] = qb2[g * 32 + c0];       ql[ks][1] = qb2[(g + 8) * 32 + c0];
            ql[ks][2] = qb2[g * 32 + c0 + 4];   ql[ks][3] = qb2[(g + 8) * 32 + c0 + 4];
        }
    }

    float Oa[8][4];
    #pragma unroll
    for (int i = 0; i < 8; i++)
        #pragma unroll
        for (int j = 0; j < 4; j++) Oa[i][j] = 0.f;
    float mr0 = -1e30f, mr1 = -1e30f, lr0 = 0.f, lr1 = 0.f;

    const uint32_t* kgh = Kh + (size_t)bh * Nseq * 32;
    const uint32_t* vgh = Vh + (size_t)bh * Nseq * 32;

    for (int kt = 0; kt < 8; kt++) {
        __syncthreads();
        #pragma unroll
        for (int i = 0; i < 4; i++) {
            int f = tid + i * 256;
            int key = f >> 3, c = f & 7;
            size_t gidx = ((size_t)(kt * 128 + key)) * 32 + c * 4;
            *(uint4*)(Khs + key * KS_STRIDE + c * 4) = *(const uint4*)(kgh + gidx);
            uint4 wv = *(const uint4*)(vgh + gidx);
            uint32_t wsv[4] = {wv.x, wv.y, wv.z, wv.w};
            #pragma unroll
            for (int s2 = 0; s2 < 4; s2++) {
                int hd0 = c * 8 + s2 * 2;
                Vh16[hd0 * (VS_STRIDE * 2) + key]       = (uint16_t)(wsv[s2] & 0xffff);
                Vh16[(hd0 + 1) * (VS_STRIDE * 2) + key] = (uint16_t)(wsv[s2] >> 16);
            }
        }
        __syncthreads();

        // S = Q K^T, 2 terms, cached K frags
        float Sf[16][4];
        #pragma unroll
        for (int ni = 0; ni < 16; ni++)
            #pragma unroll
            for (int q = 0; q < 4; q++) Sf[ni][q] = 0.f;
        #pragma unroll
        for (int ks = 0; ks < 4; ks++) {
            uint32_t bhs[16][2];
            #pragma unroll
            for (int ni = 0; ni < 16; ni++) {
                int krow = ni * 8 + g;
                bhs[ni][0] = Khs[krow * KS_STRIDE + ks * 8 + tg];
                bhs[ni][1] = Khs[krow * KS_STRIDE + ks * 8 + tg + 4];
                mma_f16(Sf[ni], qh[ks], bhs[ni]);
            }
            #pragma unroll
            for (int ni = 0; ni < 16; ni++)
                mma_f16(Sf[ni], ql[ks], bhs[ni]);
        }

        // online softmax (rows g, g+8)
        float tm0 = -1e30f, tm1 = -1e30f;
        #pragma unroll
        for (int ni = 0; ni < 16; ni++) {
            tm0 = fmaxf(tm0, fmaxf(Sf[ni][0], Sf[ni][1]));
            tm1 = fmaxf(tm1, fmaxf(Sf[ni][2], Sf[ni][3]));
        }
        tm0 = fmaxf(tm0, __shfl_xor_sync(0xffffffffu, tm0, 1));
        tm0 = fmaxf(tm0, __shfl_xor_sync(0xffffffffu, tm0, 2));
        tm1 = fmaxf(tm1, __shfl_xor_sync(0xffffffffu, tm1, 1));
        tm1 = fmaxf(tm1, __shfl_xor_sync(0xffffffffu, tm1, 2));
        float mn0 = fmaxf(mr0, tm0), mn1 = fmaxf(mr1, tm1);
        float al0 = __expf(mr0 - mn0), al1 = __expf(mr1 - mn1);
        mr0 = mn0; mr1 = mn1;
        float s0 = 0.f, s1 = 0.f;
        #pragma unroll
        for (int ni = 0; ni < 16; ni++) {
            Sf[ni][0] = __expf(Sf[ni][0] - mn0);
            Sf[ni][1] = __expf(Sf[ni][1] - mn0);
            Sf[ni][2] = __expf(Sf[ni][2] - mn1);
            Sf[ni][3] = __expf(Sf[ni][3] - mn1);
            s0 += Sf[ni][0] + Sf[ni][1];
            s1 += Sf[ni][2] + Sf[ni][3];
        }
        s0 += __shfl_xor_sync(0xffffffffu, s0, 1);
        s0 += __shfl_xor_sync(0xffffffffu, s0, 2);
        s1 += __shfl_xor_sync(0xffffffffu, s1, 1);
        s1 += __shfl_xor_sync(0xffffffffu, s1, 2);
        lr0 = lr0 * al0 + s0;
        lr1 = lr1 * al1 + s1;
        #pragma unroll
        for (int ni = 0; ni < 8; ni++) {
            Oa[ni][0] *= al0; Oa[ni][1] *= al0;
            Oa[ni][2] *= al1; Oa[ni][3] *= al1;
        }

        // O += P V, 2 terms, cached V frags
        #pragma unroll
        for (int j = 0; j < 8; j++) {
            uint32_t ph[4], pl[4];
            splitpair_h(Sf[2*j][0],   Sf[2*j][1],   ph[0], pl[0]);
            splitpair_h(Sf[2*j][2],   Sf[2*j][3],   ph[1], pl[1]);
            splitpair_h(Sf[2*j+1][0], Sf[2*j+1][1], ph[2], pl[2]);
            splitpair_h(Sf[2*j+1][2], Sf[2*j+1][3], ph[3], pl[3]);
            uint32_t vhs2[8][2];
            #pragma unroll
            for (int ni = 0; ni < 8; ni++) {
                int vrow = ni * 8 + g;
                vhs2[ni][0] = Vhs[vrow * VS_STRIDE + j * 8 + tg];
                vhs2[ni][1] = Vhs[vrow * VS_STRIDE + j * 8 + tg + 4];
                mma_f16(Oa[ni], ph, vhs2[ni]);
            }
            #pragma unroll
            for (int ni = 0; ni < 8; ni++)
                mma_f16(Oa[ni], pl, vhs2[ni]);
        }
    }

    // epilogue
    float inv0 = 1.f / lr0, inv1 = 1.f / lr1;
    int b = bh / Hh, h = bh % Hh;
    int nA = qt * 128 + wid * 16 + g;
    int nB = nA + 8;
    #pragma unroll
    for (int ni = 0; ni < 8; ni++) {
        int hd = ni * 8 + tg * 2;
        float2 vA, vB;
        vA.x = Oa[ni][0] * inv0; vA.y = Oa[ni][1] * inv0;
        vB.x = Oa[ni][2] * inv1; vB.y = Oa[ni][3] * inv1;
        size_t iA = ((size_t)b * Nseq + nA) * Cdim + h * HD + hd;
        size_t iB = ((size_t)b * Nseq + nB) * Cdim + h * HD + hd;
        *(float2*)(O + iA) = vA;
        *(float2*)(O + iB) = vB;
        uint32_t hA, lA, hB, lB;
        splitpair_h(vA.x, vA.y, hA, lA);
        splitpair_h(vB.x, vB.y, hB, lB);
        Ohi[iA >> 1] = hA; Olo[iA >> 1] = lA;
        Ohi[iB >> 1] = hB; Olo[iB >> 1] = lB;
    }
}

// ===========================================================================
extern "C" void kernel_launch(void* const* d_in, const int* in_sizes, int n_in,
                              void* d_out, int out_size)
{
    const float* x      = (const float*)d_in[0];
    const float* w_qkv  = (const float*)d_in[1];
    const float* b_qkv  = (const float*)d_in[2];
    const float* w_proj = (const float*)d_in[3];
    const float* b_proj = (const float*)d_in[4];
    const float* q_a = (const float*)d_in[5];
    const float* q_b = (const float*)d_in[6];
    const float* k_a = (const float*)d_in[7];
    const float* k_b = (const float*)d_in[8];
    const float* v_a = (const float*)d_in[9];
    const float* v_b = (const float*)d_in[10];
    const float* o_a = (const float*)d_in[11];
    const float* o_b = (const float*)d_in[12];
    float* out = (float*)d_out;

    void* sym = nullptr;
    cudaGetSymbolAddress(&sym, g_scratch);
    float* base = (float*)sym;
    float* Ob = base + F_O;
    float* XA = base + F_XA;
    float* OA = base + F_OA;
    uint32_t* xhi = (uint32_t*)(base + F_XHI);
    uint32_t* xlo = (uint32_t*)(base + F_XLO);
    uint32_t* wqh = (uint32_t*)(base + F_WQH);
    uint32_t* wph = (uint32_t*)(base + F_WPH);
    uint32_t* Qhp = (uint32_t*)(base + F_QH);
    uint32_t* Qlp = (uint32_t*)(base + F_QL);
    uint32_t* Khp = (uint32_t*)(base + F_KH);
    uint32_t* Vhp = (uint32_t*)(base + F_VH);
    uint32_t* Ohip = (uint32_t*)(base + F_OHI);
    uint32_t* Olop = (uint32_t*)(base + F_OLO);

    cudaFuncSetAttribute(gemm_f16x2_kernel<0>, cudaFuncAttributeMaxDynamicSharedMemorySize, GEMM_SMEM);
    cudaFuncSetAttribute(gemm_f16x2_kernel<1>, cudaFuncAttributeMaxDynamicSharedMemorySize, GEMM_SMEM);
    cudaFuncSetAttribute(attn_mma_kernel, cudaFuncAttributeMaxDynamicSharedMemorySize, ATT_SMEM);
    cudaFuncSetAttribute(lora_down_kernel<3>, cudaFuncAttributeMaxDynamicSharedMemorySize, 24 * Cdim * 4);
    cudaFuncSetAttribute(lora_down_kernel<1>, cudaFuncAttributeMaxDynamicSharedMemorySize, 8 * Cdim * 4);

    split_kernel<<<QKV_ELEMS / 1024, 256>>>(x, xhi, xlo);
    split_kernel<<<(3 * Cdim * Cdim) / 1024, 256>>>(w_qkv, wqh, nullptr);
    split_kernel<<<(Cdim * Cdim) / 1024, 256>>>(w_proj, wph, nullptr);

    lora_down_kernel<3><<<Mrows / 8, 256, 24 * Cdim * 4>>>(x, XA, q_a, k_a, v_a);

    gemm_f16x2_kernel<0><<<dim3(18, 64), 256, GEMM_SMEM>>>(
        xhi, xlo, wqh, b_qkv, XA, 24, q_b, k_b, v_b,
        nullptr, Qhp, Qlp, Khp, Vhp);

    attn_mma_kernel<<<dim3(8, Bsz * Hh), 256, ATT_SMEM>>>(
        Qhp, Qlp, Khp, Vhp, Ob, Ohip, Olop);

    lora_down_kernel<1><<<Mrows / 8, 256, 8 * Cdim * 4>>>(Ob, OA, o_a, o_a, o_a);

    gemm_f16x2_kernel<1><<<dim3(6, 64), 256, GEMM_SMEM>>>(
        Ohip, Olop, wph, b_proj, OA, 8, o_b, o_b, o_b,
        out, nullptr, nullptr, nullptr, nullptr);
}

// round 9
// speedup vs baseline: 1.5018x; 1.1094x over previous
#include <cuda_runtime.h>
#include <cuda_fp16.h>
#include <cstdint>

#define Bsz 8
#define Nseq 1024
#define Cdim 768
#define Hh 12
#define HD 64
#define RANK 8
#define SCALE 0.125f
#define Mrows (Bsz * Nseq)          // 8192

#define QKV_ELEMS (Bsz * Hh * Nseq * HD)   // 6291456

// float-slot offsets into g_scratch
#define F_XHI  ((size_t)0)
#define F_XLO  (F_XHI + QKV_ELEMS / 2)
#define F_WQH  (F_XLO + QKV_ELEMS / 2)
#define F_WPH  (F_WQH + (size_t)(3 * Cdim * Cdim) / 2)
#define F_QH   (F_WPH + (size_t)(Cdim * Cdim) / 2)
#define F_QL   (F_QH + QKV_ELEMS / 2)
#define F_KH   (F_QL + QKV_ELEMS / 2)
#define F_VH   (F_KH + QKV_ELEMS / 2)
#define F_OHI  (F_VH + QKV_ELEMS / 2)
#define F_OLO  (F_OHI + QKV_ELEMS / 2)
#define SCRATCH_FLOATS (F_OLO + QKV_ELEMS / 2)

__device__ float g_scratch[SCRATCH_FLOATS];

// ===========================================================================
// helpers
// ===========================================================================
__device__ __forceinline__ void mma_f16(float* c, const uint32_t* a, const uint32_t* b) {
    asm volatile("mma.sync.aligned.m16n8k16.row.col.f32.f16.f16.f32 "
        "{%0,%1,%2,%3}, {%4,%5,%6,%7}, {%8,%9}, {%0,%1,%2,%3};"
        : "+f"(c[0]), "+f"(c[1]), "+f"(c[2]), "+f"(c[3])
        : "r"(a[0]), "r"(a[1]), "r"(a[2]), "r"(a[3]), "r"(b[0]), "r"(b[1]));
}

__device__ __forceinline__ void splitpair_h(float x, float y, uint32_t& hi, uint32_t& lo) {
    __half2 h, l;
    h.x = __float2half_rn(x);
    h.y = __float2half_rn(y);
    l.x = __float2half_rn(x - __half2float(h.x));
    l.y = __float2half_rn(y - __half2float(h.y));
    hi = *reinterpret_cast<uint32_t*>(&h);
    lo = *reinterpret_cast<uint32_t*>(&l);
}
__device__ __forceinline__ uint32_t pack2h(float x, float y) {
    __half2 h;
    h.x = __float2half_rn(x);
    h.y = __float2half_rn(y);
    return *reinterpret_cast<uint32_t*>(&h);
}

// ===========================================================================
// fp16 split (x only): hi = h(v), lo = h(v - hi)
// ===========================================================================
__global__ void __launch_bounds__(256) split_kernel(
    const float* __restrict__ in, uint32_t* __restrict__ hi,
    uint32_t* __restrict__ lo)
{
    int i = blockIdx.x * 256 + threadIdx.x;
    float4 v = ((const float4*)in)[i];
    uint32_t h0, l0, h1, l1;
    splitpair_h(v.x, v.y, h0, l0);
    splitpair_h(v.z, v.w, h1, l1);
    hi[i * 2]     = h0;
    hi[i * 2 + 1] = h1;
    lo[i * 2]     = l0;
    lo[i * 2 + 1] = l1;
}

// ===========================================================================
// W_eff = W + B*A  (rank-8 update), packed to fp16 hi only.
// One block per output row d; 128 threads, 6 elems each.
// ===========================================================================
__global__ void __launch_bounds__(128) weff_kernel(
    const float* __restrict__ w, uint32_t* __restrict__ hi,
    const float* __restrict__ b0, const float* __restrict__ a0,
    const float* __restrict__ b1, const float* __restrict__ a1,
    const float* __restrict__ b2, const float* __restrict__ a2)
{
    int d = blockIdx.x;
    int sec = d / Cdim;
    int dd = d - sec * Cdim;
    const float* bb = (sec == 0) ? b0 : (sec == 1) ? b1 : b2;
    const float* aa = (sec == 0) ? a0 : (sec == 1) ? a1 : a2;
    float bv[8];
    #pragma unroll
    for (int r = 0; r < 8; r++) bv[r] = bb[dd * 8 + r];
    int c0 = threadIdx.x * 6;
    float v[6];
    #pragma unroll
    for (int i = 0; i < 6; i++) v[i] = w[(size_t)d * Cdim + c0 + i];
    #pragma unroll
    for (int r = 0; r < 8; r++) {
        float br = bv[r];
        const float* ar = aa + (size_t)r * Cdim + c0;
        #pragma unroll
        for (int i = 0; i < 6; i++) v[i] += br * ar[i];
    }
    #pragma unroll
    for (int p = 0; p < 3; p++)
        hi[(size_t)d * (Cdim / 2) + (c0 >> 1) + p] = pack2h(v[2 * p], v[2 * p + 1]);
}

// ===========================================================================
// fp16 2-term NT GEMM via mma.sync, 128x128 tile, BK=32, 8 warps.
// C = Ahi*Bhi + Alo*Bhi   (bias added; LoRA folded into B already)
// MODE 0: qkv epilogue -> Q hi+lo, K hi, V hi (u32-packed [bh][n][hd/2])
// MODE 1: proj epilogue -> fp32 out + bias
// ===========================================================================
#define GK768_U32 384
#define SROW 20
#define STAGE_U32 (3 * 128 * SROW)          // Ahi, Alo, Bhi
#define GEMM_SMEM (2 * STAGE_U32 * 4)       // 61440

template <int MODE>
__global__ void __launch_bounds__(256) gemm_f16x2_kernel(
    const uint32_t* __restrict__ Ahi, const uint32_t* __restrict__ Alo,
    const uint32_t* __restrict__ Bhi,
    const float* __restrict__ bias,
    float* __restrict__ outf,
    uint32_t* __restrict__ Qho, uint32_t* __restrict__ Qlo2,
    uint32_t* __restrict__ Kho, uint32_t* __restrict__ Vho)
{
    extern __shared__ uint32_t sm[];
    int tid = threadIdx.x;
    int wid = tid >> 5, lane = tid & 31;
    int wm = wid >> 2, wn = wid & 3;
    int m0 = blockIdx.y * 128, n0 = blockIdx.x * 128;
    int g = lane >> 2, tg = lane & 3;

    float C[4][4][4];
    #pragma unroll
    for (int a = 0; a < 4; a++)
        #pragma unroll
        for (int b = 0; b < 4; b++)
            #pragma unroll
            for (int q = 0; q < 4; q++) C[a][b][q] = 0.f;

    int row_l = tid >> 2, kq_l = tid & 3;
    int row_h = (tid + 256) >> 2;

    uint4 rg[6];
    {
        const uint32_t off = kq_l * 4;
        size_t ar0 = (size_t)(m0 + row_l) * GK768_U32 + off;
        size_t br0 = (size_t)(n0 + row_l) * GK768_U32 + off;
        size_t ar1 = (size_t)(m0 + row_h) * GK768_U32 + off;
        size_t br1 = (size_t)(n0 + row_h) * GK768_U32 + off;
        rg[0] = *(const uint4*)(Ahi + ar0); rg[1] = *(const uint4*)(Alo + ar0);
        rg[2] = *(const uint4*)(Bhi + br0);
        rg[3] = *(const uint4*)(Ahi + ar1); rg[4] = *(const uint4*)(Alo + ar1);
        rg[5] = *(const uint4*)(Bhi + br1);
    }
    {
        uint32_t* st = sm;
        uint32_t o0 = row_l * SROW + kq_l * 4;
        uint32_t o1 = row_h * SROW + kq_l * 4;
        *(uint4*)(st + o0) = rg[0];        *(uint4*)(st + 2560 + o0) = rg[1];
        *(uint4*)(st + 5120 + o0) = rg[2];
        *(uint4*)(st + o1) = rg[3];        *(uint4*)(st + 2560 + o1) = rg[4];
        *(uint4*)(st + 5120 + o1) = rg[5];
    }
    __syncthreads();

    for (int c = 0; c < 24; c++) {
        int s = c & 1;
        if (c < 23) {
            const uint32_t off = (c + 1) * 16 + kq_l * 4;
            size_t ar0 = (size_t)(m0 + row_l) * GK768_U32 + off;
            size_t br0 = (size_t)(n0 + row_l) * GK768_U32 + off;
            size_t ar1 = (size_t)(m0 + row_h) * GK768_U32 + off;
            size_t br1 = (size_t)(n0 + row_h) * GK768_U32 + off;
            rg[0] = *(const uint4*)(Ahi + ar0); rg[1] = *(const uint4*)(Alo + ar0);
            rg[2] = *(const uint4*)(Bhi + br0);
            rg[3] = *(const uint4*)(Ahi + ar1); rg[4] = *(const uint4*)(Alo + ar1);
            rg[5] = *(const uint4*)(Bhi + br1);
        }
        const uint32_t* st = sm + s * STAGE_U32;
        const uint32_t* Ah = st;
        const uint32_t* Al = st + 2560;
        const uint32_t* Bh = st + 5120;
        #pragma unroll
        for (int ks = 0; ks < 2; ks++) {
            int kp = ks * 8 + tg;
            uint32_t ah[4][4], al[4][4], bh[4][2];
            #pragma unroll
            for (int mi = 0; mi < 4; mi++) {
                int r0 = wm * 64 + mi * 16 + g;
                ah[mi][0] = Ah[r0 * SROW + kp];
                ah[mi][1] = Ah[(r0 + 8) * SROW + kp];
                ah[mi][2] = Ah[r0 * SROW + kp + 4];
                ah[mi][3] = Ah[(r0 + 8) * SROW + kp + 4];
                al[mi][0] = Al[r0 * SROW + kp];
                al[mi][1] = Al[(r0 + 8) * SROW + kp];
                al[mi][2] = Al[r0 * SROW + kp + 4];
                al[mi][3] = Al[(r0 + 8) * SROW + kp + 4];
            }
            #pragma unroll
            for (int ni = 0; ni < 4; ni++) {
                int rb = wn * 32 + ni * 8 + g;
                bh[ni][0] = Bh[rb * SROW + kp];
                bh[ni][1] = Bh[rb * SROW + kp + 4];
            }
            #pragma unroll
            for (int mi = 0; mi < 4; mi++)
                #pragma unroll
                for (int ni = 0; ni < 4; ni++)
                    mma_f16(C[mi][ni], ah[mi], bh[ni]);
            #pragma unroll
            for (int mi = 0; mi < 4; mi++)
                #pragma unroll
                for (int ni = 0; ni < 4; ni++)
                    mma_f16(C[mi][ni], al[mi], bh[ni]);
        }
        if (c < 23) {
            uint32_t* stn = sm + (s ^ 1) * STAGE_U32;
            uint32_t o0 = row_l * SROW + kq_l * 4;
            uint32_t o1 = row_h * SROW + kq_l * 4;
            *(uint4*)(stn + o0) = rg[0];        *(uint4*)(stn + 2560 + o0) = rg[1];
            *(uint4*)(stn + 5120 + o0) = rg[2];
            *(uint4*)(stn + o1) = rg[3];        *(uint4*)(stn + 2560 + o1) = rg[4];
            *(uint4*)(stn + 5120 + o1) = rg[5];
            __syncthreads();
        }
    }

    // ------------------------------ epilogue ------------------------------
    int sct = 0, dbase = 0;
    if (MODE == 0) {
        sct = n0 / Cdim;
        dbase = n0 - sct * Cdim;
    }
    #pragma unroll
    for (int mi = 0; mi < 4; mi++) {
        int m_a = m0 + wm * 64 + mi * 16 + g;
        int m_b = m_a + 8;
        int ba = m_a >> 10, na = m_a & 1023;
        int bb = m_b >> 10, nb = m_b & 1023;
        #pragma unroll
        for (int ni = 0; ni < 4; ni++) {
            int dloc = wn * 32 + ni * 8 + tg * 2;
            int d0 = n0 + dloc;
            float2 va, vb2;
            va.x  = C[mi][ni][0] + bias[d0];
            va.y  = C[mi][ni][1] + bias[d0 + 1];
            vb2.x = C[mi][ni][2] + bias[d0];
            vb2.y = C[mi][ni][3] + bias[d0 + 1];
            if (MODE == 0) {
                int dd0 = dbase + dloc;
                int h = dd0 >> 6, hd = dd0 & 63;
                size_t iA = (((size_t)(ba * Hh + h) * Nseq) + na) * 32 + (hd >> 1);
                size_t iB = (((size_t)(bb * Hh + h) * Nseq) + nb) * 32 + (hd >> 1);
                if (sct == 0) {
                    va.x *= SCALE; va.y *= SCALE; vb2.x *= SCALE; vb2.y *= SCALE;
                    uint32_t hA, lA, hB, lB;
                    splitpair_h(va.x, va.y, hA, lA);
                    splitpair_h(vb2.x, vb2.y, hB, lB);
                    Qho[iA] = hA; Qlo2[iA] = lA;
                    Qho[iB] = hB; Qlo2[iB] = lB;
                } else {
                    uint32_t* th = (sct == 1) ? Kho : Vho;
                    th[iA] = pack2h(va.x, va.y);
                    th[iB] = pack2h(vb2.x, vb2.y);
                }
            } else {
                *(float2*)(outf + (size_t)m_a * Cdim + d0) = va;
                *(float2*)(outf + (size_t)m_b * Cdim + d0) = vb2;
            }
        }
    }
}

// ===========================================================================
// Flash attention via mma.sync fp16 2-term.
// S = Qhi*Khi + Qlo*Khi;  O += Phi*Vhi + Plo*Vhi.
// Output: Ohi/Olo fp16 split only (proj GEMM input).
// ===========================================================================
#define KS_STRIDE 36
#define VS_STRIDE 67
#define ATT_SMEM_U32 (128 * KS_STRIDE + 64 * VS_STRIDE)   // 8896
#define ATT_SMEM (ATT_SMEM_U32 * 4)

__global__ void __launch_bounds__(256) attn_mma_kernel(
    const uint32_t* __restrict__ Qh, const uint32_t* __restrict__ Ql,
    const uint32_t* __restrict__ Kh, const uint32_t* __restrict__ Vh,
    uint32_t* __restrict__ Ohi, uint32_t* __restrict__ Olo)
{
    extern __shared__ uint32_t sm[];
    uint32_t* Khs = sm;                        // 128 x 36
    uint32_t* Vhs = sm + 128 * KS_STRIDE;      // 64 x 67 keypairs (transposed)
    uint16_t* Vh16 = (uint16_t*)Vhs;

    int bh = blockIdx.y, qt = blockIdx.x;
    int tid = threadIdx.x, wid = tid >> 5, lane = tid & 31;
    int g = lane >> 2, tg = lane & 3;

    uint32_t qh[4][4], ql[4][4];
    {
        const uint32_t* qb  = Qh + ((size_t)bh * Nseq + qt * 128 + wid * 16) * 32;
        const uint32_t* qb2 = Ql + ((size_t)bh * Nseq + qt * 128 + wid * 16) * 32;
        #pragma unroll
        for (int ks = 0; ks < 4; ks++) {
            int c0 = ks * 8 + tg;
            qh[ks][0] = qb[g * 32 + c0];        qh[ks][1] = qb[(g + 8) * 32 + c0];
            qh[ks][2] = qb[g * 32 + c0 + 4];    qh[ks][3] = qb[(g + 8) * 32 + c0 + 4];
            ql[ks][0] = qb2[g * 32 + c0];       ql[ks][1] = qb2[(g + 8) * 32 + c0];
            ql[ks][2] = qb2[g * 32 + c0 + 4];   ql[ks][3] = qb2[(g + 8) * 32 + c0 + 4];
        }
    }

    float Oa[8][4];
    #pragma unroll
    for (int i = 0; i < 8; i++)
        #pragma unroll
        for (int j = 0; j < 4; j++) Oa[i][j] = 0.f;
    float mr0 = -1e30f, mr1 = -1e30f, lr0 = 0.f, lr1 = 0.f;

    const uint32_t* kgh = Kh + (size_t)bh * Nseq * 32;
    const uint32_t* vgh = Vh + (size_t)bh * Nseq * 32;

    for (int kt = 0; kt < 8; kt++) {
        __syncthreads();
        #pragma unroll
        for (int i = 0; i < 4; i++) {
            int f = tid + i * 256;
            int key = f >> 3, c = f & 7;
            size_t gidx = ((size_t)(kt * 128 + key)) * 32 + c * 4;
            *(uint4*)(Khs + key * KS_STRIDE + c * 4) = *(const uint4*)(kgh + gidx);
            uint4 wv = *(const uint4*)(vgh + gidx);
            uint32_t wsv[4] = {wv.x, wv.y, wv.z, wv.w};
            #pragma unroll
            for (int s2 = 0; s2 < 4; s2++) {
                int hd0 = c * 8 + s2 * 2;
                Vh16[hd0 * (VS_STRIDE * 2) + key]       = (uint16_t)(wsv[s2] & 0xffff);
                Vh16[(hd0 + 1) * (VS_STRIDE * 2) + key] = (uint16_t)(wsv[s2] >> 16);
            }
        }
        __syncthreads();

        // S = Q K^T, 2 terms, cached K frags
        float Sf[16][4];
        #pragma unroll
        for (int ni = 0; ni < 16; ni++)
            #pragma unroll
            for (int q = 0; q < 4; q++) Sf[ni][q] = 0.f;
        #pragma unroll
        for (int ks = 0; ks < 4; ks++) {
            uint32_t bhs[16][2];
            #pragma unroll
            for (int ni = 0; ni < 16; ni++) {
                int krow = ni * 8 + g;
                bhs[ni][0] = Khs[krow * KS_STRIDE + ks * 8 + tg];
                bhs[ni][1] = Khs[krow * KS_STRIDE + ks * 8 + tg + 4];
                mma_f16(Sf[ni], qh[ks], bhs[ni]);
            }
            #pragma unroll
            for (int ni = 0; ni < 16; ni++)
                mma_f16(Sf[ni], ql[ks], bhs[ni]);
        }

        // online softmax (rows g, g+8)
        float tm0 = -1e30f, tm1 = -1e30f;
        #pragma unroll
        for (int ni = 0; ni < 16; ni++) {
            tm0 = fmaxf(tm0, fmaxf(Sf[ni][0], Sf[ni][1]));
            tm1 = fmaxf(tm1, fmaxf(Sf[ni][2], Sf[ni][3]));
        }
        tm0 = fmaxf(tm0, __shfl_xor_sync(0xffffffffu, tm0, 1));
        tm0 = fmaxf(tm0, __shfl_xor_sync(0xffffffffu, tm0, 2));
        tm1 = fmaxf(tm1, __shfl_xor_sync(0xffffffffu, tm1, 1));
        tm1 = fmaxf(tm1, __shfl_xor_sync(0xffffffffu, tm1, 2));
        float mn0 = fmaxf(mr0, tm0), mn1 = fmaxf(mr1, tm1);
        float al0 = __expf(mr0 - mn0), al1 = __expf(mr1 - mn1);
        mr0 = mn0; mr1 = mn1;
        float s0 = 0.f, s1 = 0.f;
        #pragma unroll
        for (int ni = 0; ni < 16; ni++) {
            Sf[ni][0] = __expf(Sf[ni][0] - mn0);
            Sf[ni][1] = __expf(Sf[ni][1] - mn0);
            Sf[ni][2] = __expf(Sf[ni][2] - mn1);
            Sf[ni][3] = __expf(Sf[ni][3] - mn1);
            s0 += Sf[ni][0] + Sf[ni][1];
            s1 += Sf[ni][2] + Sf[ni][3];
        }
        s0 += __shfl_xor_sync(0xffffffffu, s0, 1);
        s0 += __shfl_xor_sync(0xffffffffu, s0, 2);
        s1 += __shfl_xor_sync(0xffffffffu, s1, 1);
        s1 += __shfl_xor_sync(0xffffffffu, s1, 2);
        lr0 = lr0 * al0 + s0;
        lr1 = lr1 * al1 + s1;
        #pragma unroll
        for (int ni = 0; ni < 8; ni++) {
            Oa[ni][0] *= al0; Oa[ni][1] *= al0;
            Oa[ni][2] *= al1; Oa[ni][3] *= al1;
        }

        // O += P V, 2 terms, cached V frags
        #pragma unroll
        for (int j = 0; j < 8; j++) {
            uint32_t ph[4], pl[4];
            splitpair_h(Sf[2*j][0],   Sf[2*j][1],   ph[0], pl[0]);
            splitpair_h(Sf[2*j][2],   Sf[2*j][3],   ph[1], pl[1]);
            splitpair_h(Sf[2*j+1][0], Sf[2*j+1][1], ph[2], pl[2]);
            splitpair_h(Sf[2*j+1][2], Sf[2*j+1][3], ph[3], pl[3]);
            uint32_t vhs2[8][2];
            #pragma unroll
            for (int ni = 0; ni < 8; ni++) {
                int vrow = ni * 8 + g;
                vhs2[ni][0] = Vhs[vrow * VS_STRIDE + j * 8 + tg];
                vhs2[ni][1] = Vhs[vrow * VS_STRIDE + j * 8 + tg + 4];
                mma_f16(Oa[ni], ph, vhs2[ni]);
            }
            #pragma unroll
            for (int ni = 0; ni < 8; ni++)
                mma_f16(Oa[ni], pl, vhs2[ni]);
        }
    }

    // epilogue: Ohi/Olo fp16 split, [m][C] packed u32
    float inv0 = 1.f / lr0, inv1 = 1.f / lr1;
    int b = bh / Hh, h = bh % Hh;
    int nA = qt * 128 + wid * 16 + g;
    int nB = nA + 8;
    #pragma unroll
    for (int ni = 0; ni < 8; ni++) {
        int hd = ni * 8 + tg * 2;
        float2 vA, vB;
        vA.x = Oa[ni][0] * inv0; vA.y = Oa[ni][1] * inv0;
        vB.x = Oa[ni][2] * inv1; vB.y = Oa[ni][3] * inv1;
        size_t iA = (((size_t)b * Nseq + nA) * Cdim + h * HD + hd) >> 1;
        size_t iB = (((size_t)b * Nseq + nB) * Cdim + h * HD + hd) >> 1;
        uint32_t hA, lA, hB, lB;
        splitpair_h(vA.x, vA.y, hA, lA);
        splitpair_h(vB.x, vB.y, hB, lB);
        Ohi[iA] = hA; Olo[iA] = lA;
        Ohi[iB] = hB; Olo[iB] = lB;
    }
}

// ===========================================================================
extern "C" void kernel_launch(void* const* d_in, const int* in_sizes, int n_in,
                              void* d_out, int out_size)
{
    const float* x      = (const float*)d_in[0];
    const float* w_qkv  = (const float*)d_in[1];
    const float* b_qkv  = (const float*)d_in[2];
    const float* w_proj = (const float*)d_in[3];
    const float* b_proj = (const float*)d_in[4];
    const float* q_a = (const float*)d_in[5];
    const float* q_b = (const float*)d_in[6];
    const float* k_a = (const float*)d_in[7];
    const float* k_b = (const float*)d_in[8];
    const float* v_a = (const float*)d_in[9];
    const float* v_b = (const float*)d_in[10];
    const float* o_a = (const float*)d_in[11];
    const float* o_b = (const float*)d_in[12];
    float* out = (float*)d_out;

    void* sym = nullptr;
    cudaGetSymbolAddress(&sym, g_scratch);
    float* base = (float*)sym;
    uint32_t* xhi = (uint32_t*)(base + F_XHI);
    uint32_t* xlo = (uint32_t*)(base + F_XLO);
    uint32_t* wqh = (uint32_t*)(base + F_WQH);
    uint32_t* wph = (uint32_t*)(base + F_WPH);
    uint32_t* Qhp = (uint32_t*)(base + F_QH);
    uint32_t* Qlp = (uint32_t*)(base + F_QL);
    uint32_t* Khp = (uint32_t*)(base + F_KH);
    uint32_t* Vhp = (uint32_t*)(base + F_VH);
    uint32_t* Ohip = (uint32_t*)(base + F_OHI);
    uint32_t* Olop = (uint32_t*)(base + F_OLO);

    cudaFuncSetAttribute(gemm_f16x2_kernel<0>, cudaFuncAttributeMaxDynamicSharedMemorySize, GEMM_SMEM);
    cudaFuncSetAttribute(gemm_f16x2_kernel<1>, cudaFuncAttributeMaxDynamicSharedMemorySize, GEMM_SMEM);
    cudaFuncSetAttribute(attn_mma_kernel, cudaFuncAttributeMaxDynamicSharedMemorySize, ATT_SMEM);

    // x -> hi/lo fp16
    split_kernel<<<QKV_ELEMS / 1024, 256>>>(x, xhi, xlo);
    // W_eff = W + B*A, packed fp16 hi
    weff_kernel<<<3 * Cdim, 128>>>(w_qkv, wqh, q_b, q_a, k_b, k_a, v_b, v_a);
    weff_kernel<<<Cdim, 128>>>(w_proj, wph, o_b, o_a, o_b, o_a, o_b, o_a);

    // QKV GEMM + bias (+SCALE on q) -> Q hi/lo, K hi, V hi
    gemm_f16x2_kernel<0><<<dim3(18, 64), 256, GEMM_SMEM>>>(
        xhi, xlo, wqh, b_qkv, nullptr, Qhp, Qlp, Khp, Vhp);

    // Attention -> Ohi/Olo
    attn_mma_kernel<<<dim3(8, Bsz * Hh), 256, ATT_SMEM>>>(
        Qhp, Qlp, Khp, Vhp, Ohip, Olop);

    // Output projection + bias -> out
    gemm_f16x2_kernel<1><<<dim3(6, 64), 256, GEMM_SMEM>>>(
        Ohip, Olop, wph, b_proj, out, nullptr, nullptr, nullptr, nullptr);
}

// round 10
// speedup vs baseline: 1.7261x; 1.1494x over previous
#include <cuda_runtime.h>
#include <cuda_fp16.h>
#include <cstdint>

#define Bsz 8
#define Nseq 1024
#define Cdim 768
#define Hh 12
#define HD 64
#define RANK 8
#define SCALE 0.125f
#define Mrows (Bsz * Nseq)          // 8192

#define QKV_ELEMS (Bsz * Hh * Nseq * HD)   // 6291456

// float-slot offsets into g_scratch
#define F_XHI  ((size_t)0)
#define F_XLO  (F_XHI + QKV_ELEMS / 2)
#define F_WQH  (F_XLO + QKV_ELEMS / 2)
#define F_WPH  (F_WQH + (size_t)(3 * Cdim * Cdim) / 2)
#define F_QH   (F_WPH + (size_t)(Cdim * Cdim) / 2)
#define F_QL   (F_QH + QKV_ELEMS / 2)
#define F_KH   (F_QL + QKV_ELEMS / 2)
#define F_VH   (F_KH + QKV_ELEMS / 2)
#define F_OHI  (F_VH + QKV_ELEMS / 2)
#define F_OLO  (F_OHI + QKV_ELEMS / 2)
#define SCRATCH_FLOATS (F_OLO + QKV_ELEMS / 2)

__device__ float g_scratch[SCRATCH_FLOATS];

// ===========================================================================
// helpers
// ===========================================================================
__device__ __forceinline__ uint32_t smem_u32(const void* p) {
    uint32_t a;
    asm("{ .reg .u64 t; cvta.to.shared.u64 t, %1; cvt.u32.u64 %0, t; }" : "=r"(a) : "l"(p));
    return a;
}
__device__ __forceinline__ void cp_async16(uint32_t dst, const void* src) {
    asm volatile("cp.async.cg.shared.global [%0], [%1], 16;" :: "r"(dst), "l"(src) : "memory");
}
__device__ __forceinline__ void mma_f16(float* c, const uint32_t* a, const uint32_t* b) {
    asm volatile("mma.sync.aligned.m16n8k16.row.col.f32.f16.f16.f32 "
        "{%0,%1,%2,%3}, {%4,%5,%6,%7}, {%8,%9}, {%0,%1,%2,%3};"
        : "+f"(c[0]), "+f"(c[1]), "+f"(c[2]), "+f"(c[3])
        : "r"(a[0]), "r"(a[1]), "r"(a[2]), "r"(a[3]), "r"(b[0]), "r"(b[1]));
}

__device__ __forceinline__ void splitpair_h(float x, float y, uint32_t& hi, uint32_t& lo) {
    __half2 h, l;
    h.x = __float2half_rn(x);
    h.y = __float2half_rn(y);
    l.x = __float2half_rn(x - __half2float(h.x));
    l.y = __float2half_rn(y - __half2float(h.y));
    hi = *reinterpret_cast<uint32_t*>(&h);
    lo = *reinterpret_cast<uint32_t*>(&l);
}
__device__ __forceinline__ uint32_t pack2h(float x, float y) {
    __half2 h;
    h.x = __float2half_rn(x);
    h.y = __float2half_rn(y);
    return *reinterpret_cast<uint32_t*>(&h);
}

// ===========================================================================
// fp16 split (x only)
// ===========================================================================
__global__ void __launch_bounds__(256) split_kernel(
    const float* __restrict__ in, uint32_t* __restrict__ hi,
    uint32_t* __restrict__ lo)
{
    int i = blockIdx.x * 256 + threadIdx.x;
    float4 v = ((const float4*)in)[i];
    uint32_t h0, l0, h1, l1;
    splitpair_h(v.x, v.y, h0, l0);
    splitpair_h(v.z, v.w, h1, l1);
    hi[i * 2]     = h0;
    hi[i * 2 + 1] = h1;
    lo[i * 2]     = l0;
    lo[i * 2 + 1] = l1;
}

// ===========================================================================
// W_eff = W + B*A  (rank-8 update), packed to fp16 hi only.
// ===========================================================================
__global__ void __launch_bounds__(128) weff_kernel(
    const float* __restrict__ w, uint32_t* __restrict__ hi,
    const float* __restrict__ b0, const float* __restrict__ a0,
    const float* __restrict__ b1, const float* __restrict__ a1,
    const float* __restrict__ b2, const float* __restrict__ a2)
{
    int d = blockIdx.x;
    int sec = d / Cdim;
    int dd = d - sec * Cdim;
    const float* bb = (sec == 0) ? b0 : (sec == 1) ? b1 : b2;
    const float* aa = (sec == 0) ? a0 : (sec == 1) ? a1 : a2;
    float bv[8];
    #pragma unroll
    for (int r = 0; r < 8; r++) bv[r] = bb[dd * 8 + r];
    int c0 = threadIdx.x * 6;
    float v[6];
    #pragma unroll
    for (int i = 0; i < 6; i++) v[i] = w[(size_t)d * Cdim + c0 + i];
    #pragma unroll
    for (int r = 0; r < 8; r++) {
        float br = bv[r];
        const float* ar = aa + (size_t)r * Cdim + c0;
        #pragma unroll
        for (int i = 0; i < 6; i++) v[i] += br * ar[i];
    }
    #pragma unroll
    for (int p = 0; p < 3; p++)
        hi[(size_t)d * (Cdim / 2) + (c0 >> 1) + p] = pack2h(v[2 * p], v[2 * p + 1]);
}

// ===========================================================================
// fp16 2-term NT GEMM, 128x128 tile, BK=32, 8 warps, cp.async pipeline,
// 2 CTAs/SM.
// ===========================================================================
#define GK768_U32 384
#define SROW 20
#define STAGE_U32 (3 * 128 * SROW)          // Ahi, Alo, Bhi
#define STAGE_BYTES (STAGE_U32 * 4)         // 30720
#define GEMM_SMEM (2 * STAGE_BYTES)         // 61440

template <int MODE>
__global__ void __launch_bounds__(256, 2) gemm_f16x2_kernel(
    const uint32_t* __restrict__ Ahi, const uint32_t* __restrict__ Alo,
    const uint32_t* __restrict__ Bhi,
    const float* __restrict__ bias,
    float* __restrict__ outf,
    uint32_t* __restrict__ Qho, uint32_t* __restrict__ Qlo2,
    uint32_t* __restrict__ Kho, uint32_t* __restrict__ Vho)
{
    extern __shared__ uint32_t sm[];
    uint32_t sbase = smem_u32(sm);
    int tid = threadIdx.x;
    int wid = tid >> 5, lane = tid & 31;
    int wm = wid >> 2, wn = wid & 3;
    int m0 = blockIdx.y * 128, n0 = blockIdx.x * 128;
    int g = lane >> 2, tg = lane & 3;

    float C[4][4][4];
    #pragma unroll
    for (int a = 0; a < 4; a++)
        #pragma unroll
        for (int b = 0; b < 4; b++)
            #pragma unroll
            for (int q = 0; q < 4; q++) C[a][b][q] = 0.f;

    int row_l = tid >> 2, kq_l = tid & 3;
    int row_h = (tid + 256) >> 2;

    // per-thread smem dst offsets (bytes)
    uint32_t d0b = (row_l * SROW + kq_l * 4) * 4;
    uint32_t d1b = (row_h * SROW + kq_l * 4) * 4;
    const uint32_t* Asrc0 = Ahi + (size_t)(m0 + row_l) * GK768_U32 + kq_l * 4;
    const uint32_t* Lsrc0 = Alo + (size_t)(m0 + row_l) * GK768_U32 + kq_l * 4;
    const uint32_t* Bsrc0 = Bhi + (size_t)(n0 + row_l) * GK768_U32 + kq_l * 4;
    const uint32_t* Asrc1 = Ahi + (size_t)(m0 + row_h) * GK768_U32 + kq_l * 4;
    const uint32_t* Lsrc1 = Alo + (size_t)(m0 + row_h) * GK768_U32 + kq_l * 4;
    const uint32_t* Bsrc1 = Bhi + (size_t)(n0 + row_h) * GK768_U32 + kq_l * 4;

    // prologue: chunk 0 -> buffer 0
    {
        uint32_t db = sbase;
        cp_async16(db + d0b,                Asrc0);
        cp_async16(db + 2560 * 4 + d0b,     Lsrc0);
        cp_async16(db + 5120 * 4 + d0b,     Bsrc0);
        cp_async16(db + d1b,                Asrc1);
        cp_async16(db + 2560 * 4 + d1b,     Lsrc1);
        cp_async16(db + 5120 * 4 + d1b,     Bsrc1);
        asm volatile("cp.async.commit_group;" ::: "memory");
    }

    for (int c = 0; c < 24; c++) {
        int s = c & 1;
        if (c < 23) {
            uint32_t off = (c + 1) * 16;
            uint32_t db = sbase + (s ^ 1) * STAGE_BYTES;
            cp_async16(db + d0b,            Asrc0 + off);
            cp_async16(db + 2560 * 4 + d0b, Lsrc0 + off);
            cp_async16(db + 5120 * 4 + d0b, Bsrc0 + off);
            cp_async16(db + d1b,            Asrc1 + off);
            cp_async16(db + 2560 * 4 + d1b, Lsrc1 + off);
            cp_async16(db + 5120 * 4 + d1b, Bsrc1 + off);
            asm volatile("cp.async.commit_group;" ::: "memory");
            asm volatile("cp.async.wait_group 1;" ::: "memory");
        } else {
            asm volatile("cp.async.wait_group 0;" ::: "memory");
        }
        __syncthreads();

        const uint32_t* st = sm + s * STAGE_U32;
        const uint32_t* Ah = st;
        const uint32_t* Al = st + 2560;
        const uint32_t* Bh = st + 5120;
        #pragma unroll
        for (int ks = 0; ks < 2; ks++) {
            int kp = ks * 8 + tg;
            uint32_t ah[4][4], al[4][4], bh[4][2];
            #pragma unroll
            for (int mi = 0; mi < 4; mi++) {
                int r0 = wm * 64 + mi * 16 + g;
                ah[mi][0] = Ah[r0 * SROW + kp];
                ah[mi][1] = Ah[(r0 + 8) * SROW + kp];
                ah[mi][2] = Ah[r0 * SROW + kp + 4];
                ah[mi][3] = Ah[(r0 + 8) * SROW + kp + 4];
                al[mi][0] = Al[r0 * SROW + kp];
                al[mi][1] = Al[(r0 + 8) * SROW + kp];
                al[mi][2] = Al[r0 * SROW + kp + 4];
                al[mi][3] = Al[(r0 + 8) * SROW + kp + 4];
            }
            #pragma unroll
            for (int ni = 0; ni < 4; ni++) {
                int rb = wn * 32 + ni * 8 + g;
                bh[ni][0] = Bh[rb * SROW + kp];
                bh[ni][1] = Bh[rb * SROW + kp + 4];
            }
            #pragma unroll
            for (int mi = 0; mi < 4; mi++)
                #pragma unroll
                for (int ni = 0; ni < 4; ni++)
                    mma_f16(C[mi][ni], ah[mi], bh[ni]);
            #pragma unroll
            for (int mi = 0; mi < 4; mi++)
                #pragma unroll
                for (int ni = 0; ni < 4; ni++)
                    mma_f16(C[mi][ni], al[mi], bh[ni]);
        }
        __syncthreads();
    }

    // ------------------------------ epilogue ------------------------------
    int sct = 0, dbase = 0;
    if (MODE == 0) {
        sct = n0 / Cdim;
        dbase = n0 - sct * Cdim;
    }
    #pragma unroll
    for (int mi = 0; mi < 4; mi++) {
        int m_a = m0 + wm * 64 + mi * 16 + g;
        int m_b = m_a + 8;
        int ba = m_a >> 10, na = m_a & 1023;
        int bb = m_b >> 10, nb = m_b & 1023;
        #pragma unroll
        for (int ni = 0; ni < 4; ni++) {
            int dloc = wn * 32 + ni * 8 + tg * 2;
            int d0 = n0 + dloc;
            float2 va, vb2;
            va.x  = C[mi][ni][0] + bias[d0];
            va.y  = C[mi][ni][1] + bias[d0 + 1];
            vb2.x = C[mi][ni][2] + bias[d0];
            vb2.y = C[mi][ni][3] + bias[d0 + 1];
            if (MODE == 0) {
                int dd0 = dbase + dloc;
                int h = dd0 >> 6, hd = dd0 & 63;
                size_t iA = (((size_t)(ba * Hh + h) * Nseq) + na) * 32 + (hd >> 1);
                size_t iB = (((size_t)(bb * Hh + h) * Nseq) + nb) * 32 + (hd >> 1);
                if (sct == 0) {
                    va.x *= SCALE; va.y *= SCALE; vb2.x *= SCALE; vb2.y *= SCALE;
                    uint32_t hA, lA, hB, lB;
                    splitpair_h(va.x, va.y, hA, lA);
                    splitpair_h(vb2.x, vb2.y, hB, lB);
                    Qho[iA] = hA; Qlo2[iA] = lA;
                    Qho[iB] = hB; Qlo2[iB] = lB;
                } else {
                    uint32_t* th = (sct == 1) ? Kho : Vho;
                    th[iA] = pack2h(va.x, va.y);
                    th[iB] = pack2h(vb2.x, vb2.y);
                }
            } else {
                *(float2*)(outf + (size_t)m_a * Cdim + d0) = va;
                *(float2*)(outf + (size_t)m_b * Cdim + d0) = vb2;
            }
        }
    }
}

// ===========================================================================
// Flash attention via mma.sync fp16 2-term (unchanged from R9).
// ===========================================================================
#define KS_STRIDE 36
#define VS_STRIDE 67
#define ATT_SMEM_U32 (128 * KS_STRIDE + 64 * VS_STRIDE)   // 8896
#define ATT_SMEM (ATT_SMEM_U32 * 4)

__global__ void __launch_bounds__(256) attn_mma_kernel(
    const uint32_t* __restrict__ Qh, const uint32_t* __restrict__ Ql,
    const uint32_t* __restrict__ Kh, const uint32_t* __restrict__ Vh,
    uint32_t* __restrict__ Ohi, uint32_t* __restrict__ Olo)
{
    extern __shared__ uint32_t sm[];
    uint32_t* Khs = sm;
    uint32_t* Vhs = sm + 128 * KS_STRIDE;
    uint16_t* Vh16 = (uint16_t*)Vhs;

    int bh = blockIdx.y, qt = blockIdx.x;
    int tid = threadIdx.x, wid = tid >> 5, lane = tid & 31;
    int g = lane >> 2, tg = lane & 3;

    uint32_t qh[4][4], ql[4][4];
    {
        const uint32_t* qb  = Qh + ((size_t)bh * Nseq + qt * 128 + wid * 16) * 32;
        const uint32_t* qb2 = Ql + ((size_t)bh * Nseq + qt * 128 + wid * 16) * 32;
        #pragma unroll
        for (int ks = 0; ks < 4; ks++) {
            int c0 = ks * 8 + tg;
            qh[ks][0] = qb[g * 32 + c0];        qh[ks][1] = qb[(g + 8) * 32 + c0];
            qh[ks][2] = qb[g * 32 + c0 + 4];    qh[ks][3] = qb[(g + 8) * 32 + c0 + 4];
            ql[ks][0] = qb2[g * 32 + c0];       ql[ks][1] = qb2[(g + 8) * 32 + c0];
            ql[ks][2] = qb2[g * 32 + c0 + 4];   ql[ks][3] = qb2[(g + 8) * 32 + c0 + 4];
        }
    }

    float Oa[8][4];
    #pragma unroll
    for (int i = 0; i < 8; i++)
        #pragma unroll
        for (int j = 0; j < 4; j++) Oa[i][j] = 0.f;
    float mr0 = -1e30f, mr1 = -1e30f, lr0 = 0.f, lr1 = 0.f;

    const uint32_t* kgh = Kh + (size_t)bh * Nseq * 32;
    const uint32_t* vgh = Vh + (size_t)bh * Nseq * 32;

    for (int kt = 0; kt < 8; kt++) {
        __syncthreads();
        #pragma unroll
        for (int i = 0; i < 4; i++) {
            int f = tid + i * 256;
            int key = f >> 3, c = f & 7;
            size_t gidx = ((size_t)(kt * 128 + key)) * 32 + c * 4;
            *(uint4*)(Khs + key * KS_STRIDE + c * 4) = *(const uint4*)(kgh + gidx);
            uint4 wv = *(const uint4*)(vgh + gidx);
            uint32_t wsv[4] = {wv.x, wv.y, wv.z, wv.w};
            #pragma unroll
            for (int s2 = 0; s2 < 4; s2++) {
                int hd0 = c * 8 + s2 * 2;
                Vh16[hd0 * (VS_STRIDE * 2) + key]       = (uint16_t)(wsv[s2] & 0xffff);
                Vh16[(hd0 + 1) * (VS_STRIDE * 2) + key] = (uint16_t)(wsv[s2] >> 16);
            }
        }
        __syncthreads();

        float Sf[16][4];
        #pragma unroll
        for (int ni = 0; ni < 16; ni++)
            #pragma unroll
            for (int q = 0; q < 4; q++) Sf[ni][q] = 0.f;
        #pragma unroll
        for (int ks = 0; ks < 4; ks++) {
            uint32_t bhs[16][2];
            #pragma unroll
            for (int ni = 0; ni < 16; ni++) {
                int krow = ni * 8 + g;
                bhs[ni][0] = Khs[krow * KS_STRIDE + ks * 8 + tg];
                bhs[ni][1] = Khs[krow * KS_STRIDE + ks * 8 + tg + 4];
                mma_f16(Sf[ni], qh[ks], bhs[ni]);
            }
            #pragma unroll
            for (int ni = 0; ni < 16; ni++)
                mma_f16(Sf[ni], ql[ks], bhs[ni]);
        }

        float tm0 = -1e30f, tm1 = -1e30f;
        #pragma unroll
        for (int ni = 0; ni < 16; ni++) {
            tm0 = fmaxf(tm0, fmaxf(Sf[ni][0], Sf[ni][1]));
            tm1 = fmaxf(tm1, fmaxf(Sf[ni][2], Sf[ni][3]));
        }
        tm0 = fmaxf(tm0, __shfl_xor_sync(0xffffffffu, tm0, 1));
        tm0 = fmaxf(tm0, __shfl_xor_sync(0xffffffffu, tm0, 2));
        tm1 = fmaxf(tm1, __shfl_xor_sync(0xffffffffu, tm1, 1));
        tm1 = fmaxf(tm1, __shfl_xor_sync(0xffffffffu, tm1, 2));
        float mn0 = fmaxf(mr0, tm0), mn1 = fmaxf(mr1, tm1);
        float al0 = __expf(mr0 - mn0), al1 = __expf(mr1 - mn1);
        mr0 = mn0; mr1 = mn1;
        float s0 = 0.f, s1 = 0.f;
        #pragma unroll
        for (int ni = 0; ni < 16; ni++) {
            Sf[ni][0] = __expf(Sf[ni][0] - mn0);
            Sf[ni][1] = __expf(Sf[ni][1] - mn0);
            Sf[ni][2] = __expf(Sf[ni][2] - mn1);
            Sf[ni][3] = __expf(Sf[ni][3] - mn1);
            s0 += Sf[ni][0] + Sf[ni][1];
            s1 += Sf[ni][2] + Sf[ni][3];
        }
        s0 += __shfl_xor_sync(0xffffffffu, s0, 1);
        s0 += __shfl_xor_sync(0xffffffffu, s0, 2);
        s1 += __shfl_xor_sync(0xffffffffu, s1, 1);
        s1 += __shfl_xor_sync(0xffffffffu, s1, 2);
        lr0 = lr0 * al0 + s0;
        lr1 = lr1 * al1 + s1;
        #pragma unroll
        for (int ni = 0; ni < 8; ni++) {
            Oa[ni][0] *= al0; Oa[ni][1] *= al0;
            Oa[ni][2] *= al1; Oa[ni][3] *= al1;
        }

        #pragma unroll
        for (int j = 0; j < 8; j++) {
            uint32_t ph[4], pl[4];
            splitpair_h(Sf[2*j][0],   Sf[2*j][1],   ph[0], pl[0]);
            splitpair_h(Sf[2*j][2],   Sf[2*j][3],   ph[1], pl[1]);
            splitpair_h(Sf[2*j+1][0], Sf[2*j+1][1], ph[2], pl[2]);
            splitpair_h(Sf[2*j+1][2], Sf[2*j+1][3], ph[3], pl[3]);
            uint32_t vhs2[8][2];
            #pragma unroll
            for (int ni = 0; ni < 8; ni++) {
                int vrow = ni * 8 + g;
                vhs2[ni][0] = Vhs[vrow * VS_STRIDE + j * 8 + tg];
                vhs2[ni][1] = Vhs[vrow * VS_STRIDE + j * 8 + tg + 4];
                mma_f16(Oa[ni], ph, vhs2[ni]);
            }
            #pragma unroll
            for (int ni = 0; ni < 8; ni++)
                mma_f16(Oa[ni], pl, vhs2[ni]);
        }
    }

    float inv0 = 1.f / lr0, inv1 = 1.f / lr1;
    int b = bh / Hh, h = bh % Hh;
    int nA = qt * 128 + wid * 16 + g;
    int nB = nA + 8;
    #pragma unroll
    for (int ni = 0; ni < 8; ni++) {
        int hd = ni * 8 + tg * 2;
        float2 vA, vB;
        vA.x = Oa[ni][0] * inv0; vA.y = Oa[ni][1] * inv0;
        vB.x = Oa[ni][2] * inv1; vB.y = Oa[ni][3] * inv1;
        size_t iA = (((size_t)b * Nseq + nA) * Cdim + h * HD + hd) >> 1;
        size_t iB = (((size_t)b * Nseq + nB) * Cdim + h * HD + hd) >> 1;
        uint32_t hA, lA, hB, lB;
        splitpair_h(vA.x, vA.y, hA, lA);
        splitpair_h(vB.x, vB.y, hB, lB);
        Ohi[iA] = hA; Olo[iA] = lA;
        Ohi[iB] = hB; Olo[iB] = lB;
    }
}

// ===========================================================================
extern "C" void kernel_launch(void* const* d_in, const int* in_sizes, int n_in,
                              void* d_out, int out_size)
{
    const float* x      = (const float*)d_in[0];
    const float* w_qkv  = (const float*)d_in[1];
    const float* b_qkv  = (const float*)d_in[2];
    const float* w_proj = (const float*)d_in[3];
    const float* b_proj = (const float*)d_in[4];
    const float* q_a = (const float*)d_in[5];
    const float* q_b = (const float*)d_in[6];
    const float* k_a = (const float*)d_in[7];
    const float* k_b = (const float*)d_in[8];
    const float* v_a = (const float*)d_in[9];
    const float* v_b = (const float*)d_in[10];
    const float* o_a = (const float*)d_in[11];
    const float* o_b = (const float*)d_in[12];
    float* out = (float*)d_out;

    void* sym = nullptr;
    cudaGetSymbolAddress(&sym, g_scratch);
    float* base = (float*)sym;
    uint32_t* xhi = (uint32_t*)(base + F_XHI);
    uint32_t* xlo = (uint32_t*)(base + F_XLO);
    uint32_t* wqh = (uint32_t*)(base + F_WQH);
    uint32_t* wph = (uint32_t*)(base + F_WPH);
    uint32_t* Qhp = (uint32_t*)(base + F_QH);
    uint32_t* Qlp = (uint32_t*)(base + F_QL);
    uint32_t* Khp = (uint32_t*)(base + F_KH);
    uint32_t* Vhp = (uint32_t*)(base + F_VH);
    uint32_t* Ohip = (uint32_t*)(base + F_OHI);
    uint32_t* Olop = (uint32_t*)(base + F_OLO);

    cudaFuncSetAttribute(gemm_f16x2_kernel<0>, cudaFuncAttributeMaxDynamicSharedMemorySize, GEMM_SMEM);
    cudaFuncSetAttribute(gemm_f16x2_kernel<1>, cudaFuncAttributeMaxDynamicSharedMemorySize, GEMM_SMEM);
    cudaFuncSetAttribute(attn_mma_kernel, cudaFuncAttributeMaxDynamicSharedMemorySize, ATT_SMEM);

    split_kernel<<<QKV_ELEMS / 1024, 256>>>(x, xhi, xlo);
    weff_kernel<<<3 * Cdim, 128>>>(w_qkv, wqh, q_b, q_a, k_b, k_a, v_b, v_a);
    weff_kernel<<<Cdim, 128>>>(w_proj, wph, o_b, o_a, o_b, o_a, o_b, o_a);

    gemm_f16x2_kernel<0><<<dim3(18, 64), 256, GEMM_SMEM>>>(
        xhi, xlo, wqh, b_qkv, nullptr, Qhp, Qlp, Khp, Vhp);

    attn_mma_kernel<<<dim3(8, Bsz * Hh), 256, ATT_SMEM>>>(
        Qhp, Qlp, Khp, Vhp, Ohip, Olop);

    gemm_f16x2_kernel<1><<<dim3(6, 64), 256, GEMM_SMEM>>>(
        Ohip, Olop, wph, b_proj, out, nullptr, nullptr, nullptr, nullptr);
}